// round 12
// baseline (speedup 1.0000x reference)
#include <cuda_runtime.h>
#include <cuda_fp16.h>
#include <math.h>
#include <stdint.h>

// Problem constants
#define BB 16
#define TT 1024
#define DD 512
#define MTOT (BB * TT)                  // 16384
#define SCALE 0.04419417382415922f      // 1/sqrt(512)

// =================== helpers (plain sm_80+ features only) ==================
__device__ __forceinline__ uint32_t smem_u32_of(const void* p) {
    uint32_t a;
    asm("{ .reg .u64 t; cvta.to.shared.u64 t, %1; cvt.u32.u64 %0, t; }"
        : "=r"(a) : "l"(p));
    return a;
}
__device__ __forceinline__ void cpa16(uint32_t dst, const void* src) {
    asm volatile("cp.async.cg.shared.global [%0], [%1], 16;"
                 :: "r"(dst), "l"(src));
}
__device__ __forceinline__ void cpa16z(uint32_t dst, const void* src, int sz) {
    asm volatile("cp.async.cg.shared.global [%0], [%1], 16, %2;"
                 :: "r"(dst), "l"(src), "r"(sz));
}
#define CP_COMMIT() asm volatile("cp.async.commit_group;" ::: "memory")
#define CP_WAIT0()  asm volatile("cp.async.wait_group 0;" ::: "memory")
#define CP_WAIT1()  asm volatile("cp.async.wait_group 1;" ::: "memory")

__device__ __forceinline__ void ldm4(uint32_t r[4], uint32_t addr) {
    asm volatile("ldmatrix.sync.aligned.m8n8.x4.shared.b16 {%0,%1,%2,%3}, [%4];"
                 : "=r"(r[0]), "=r"(r[1]), "=r"(r[2]), "=r"(r[3]) : "r"(addr));
}
#define MMA_F16(c, a, b0, b1)                                                  \
    asm volatile("mma.sync.aligned.m16n8k16.row.col.f32.f16.f16.f32 "          \
        "{%0,%1,%2,%3},{%4,%5,%6,%7},{%8,%9},{%0,%1,%2,%3};"                   \
        : "+f"((c)[0]), "+f"((c)[1]), "+f"((c)[2]), "+f"((c)[3])               \
        : "r"((a)[0]), "r"((a)[1]), "r"((a)[2]), "r"((a)[3]),                  \
          "r"(b0), "r"(b1))

__device__ __forceinline__ uint32_t sw128(uint32_t off) {
    return off ^ ((off >> 3) & 0x70);
}

// =================== scratch (fp16; ~151 MB) ===============================
__device__ __half g_Qh[MTOT * DD], g_Ql[MTOT * DD];       // Q pair (scores A)
__device__ __half g_Kh[MTOT * DD];                        // K hi (scores B)
__device__ __half g_Vth[MTOT * DD];                       // V^T hi [b][d][t]
__device__ __half g_Sh[BB * TT * TT], g_Sl[BB * TT * TT]; // logits pair -> probs hi
// dead-buffer aliases (lifetimes verified disjoint)
#define g_valh g_Qh
#define g_hh   g_Kh
#define g_enhh g_Vth
// transposed weights [N, K], hi plane only
__device__ __half g_Wqt[DD * DD];
__device__ __half g_Wkt[DD * DD];
__device__ __half g_Wvt[DD * DD];
__device__ __half g_Wc1t[DD * 1536];
__device__ __half g_Wc2t[DD * DD];
__device__ __half g_Wft[DD * 1024];

__device__ __forceinline__ void split2(float v, __half& h, __half& l) {
    h = __float2half(v);
    l = __float2half(v - __half2float(h));
}
__device__ __forceinline__ void split_pack(float v0, float v1,
                                           uint32_t& hp, uint32_t& lp) {
    __half h0, l0, h1, l1;
    split2(v0, h0, l0);
    split2(v1, h1, l1);
    hp = (uint32_t)__half_as_ushort(h0) | ((uint32_t)__half_as_ushort(h1) << 16);
    lp = (uint32_t)__half_as_ushort(l0) | ((uint32_t)__half_as_ushort(l1) << 16);
}
__device__ __forceinline__ int vlen_of(const int* __restrict__ vl, int b) {
    int stride = (vl[1] == 0) ? 2 : 1;   // int64 vs int32 (values in [1,1024])
    return vl[b * stride];
}

// =================== prep: all 6 weight transposes in one launch ===========
__global__ __launch_bounds__(256)
void wtrans6_kernel(const float* __restrict__ W0, const float* __restrict__ W1,
                    const float* __restrict__ W2, const float* __restrict__ W3,
                    const float* __restrict__ W4, const float* __restrict__ W5,
                    __half* __restrict__ T0, __half* __restrict__ T1,
                    __half* __restrict__ T2, __half* __restrict__ T3,
                    __half* __restrict__ T4, __half* __restrict__ T5) {
    int z = blockIdx.z;
    const float* W = (z == 0) ? W0 : (z == 1) ? W1 : (z == 2) ? W2
                   : (z == 3) ? W3 : (z == 4) ? W4 : W5;
    __half* T = (z == 0) ? T0 : (z == 1) ? T1 : (z == 2) ? T2
              : (z == 3) ? T3 : (z == 4) ? T4 : T5;
    int K = (z == 3) ? 1536 : (z == 5) ? 1024 : 512;
    int k0 = blockIdx.y * 32;
    if (k0 >= K) return;
    __shared__ float t[32][33];
    int n0 = blockIdx.x * 32;
    int tx = threadIdx.x & 31, ty = threadIdx.x >> 5;
    for (int i = ty; i < 32; i += 8)
        t[i][tx] = W[(size_t)(k0 + i) * 512 + n0 + tx];
    __syncthreads();
    for (int i = ty; i < 32; i += 8)
        T[(size_t)(n0 + i) * K + k0 + tx] = __float2half(t[tx][i]);
}

// =================== masked softmax: logits pair -> probs hi ===============
__global__ __launch_bounds__(256)
void softmax_kernel(const int* __restrict__ vl) {
    __shared__ float red[8];
    int row = blockIdx.x;
    int b = row >> 10;
    int L = vlen_of(vl, b);
    size_t rbase = (size_t)row * TT;
    int tid = threadIdx.x, lane = tid & 31, wid = tid >> 5;
    int k0 = tid * 4;
    float xs[4];
#pragma unroll
    for (int c = 0; c < 4; c++)
        xs[c] = __half2float(g_Sh[rbase + k0 + c]) +
                __half2float(g_Sl[rbase + k0 + c]);
    float m = -3.4e38f;
#pragma unroll
    for (int c = 0; c < 4; c++)
        if (k0 + c < L) m = fmaxf(m, xs[c]);
#pragma unroll
    for (int s = 16; s > 0; s >>= 1)
        m = fmaxf(m, __shfl_xor_sync(0xffffffffu, m, s));
    if (lane == 0) red[wid] = m;
    __syncthreads();
    if (wid == 0) {
        float t = red[lane & 7];
#pragma unroll
        for (int s = 4; s > 0; s >>= 1)
            t = fmaxf(t, __shfl_xor_sync(0xffffffffu, t, s));
        if (lane == 0) red[0] = t;
    }
    __syncthreads();
    float rm = red[0];
    float e[4], sum = 0.f;
#pragma unroll
    for (int c = 0; c < 4; c++) {
        e[c] = (k0 + c < L) ? expf(xs[c] - rm) : 0.f;
        sum += e[c];
    }
#pragma unroll
    for (int s = 16; s > 0; s >>= 1)
        sum += __shfl_xor_sync(0xffffffffu, sum, s);
    __syncthreads();
    if (lane == 0) red[wid] = sum;
    __syncthreads();
    if (wid == 0) {
        float t = red[lane & 7];
#pragma unroll
        for (int s = 4; s > 0; s >>= 1)
            t += __shfl_xor_sync(0xffffffffu, t, s);
        if (lane == 0) red[0] = t;
    }
    __syncthreads();
    float inv = 1.f / red[0];
    __half hb[4];
#pragma unroll
    for (int c = 0; c < 4; c++)
        hb[c] = __float2half(e[c] * inv);
    *reinterpret_cast<uint2*>(&g_Sh[rbase + k0]) =
        *reinterpret_cast<uint2*>(hb);
}

// ===== mma.sync GEMM, 128x128 tiles, 256 threads, 3-stage, 2 CTAs/SM ======
// MODE: 0=Qproj 1=Kproj 2=Vproj(T out) 3=scores(A dual) 4=PV 5=conv1 6=gate 7=final
// Stage (single-A): [Ah 16K][Bh 16K] = 32 KB x3 = 96 KB  -> 2 CTAs/SM
// Stage (dual-A, scores): [Ah 16K][Al 16K][Bh 16K] = 48 KB x3 = 144 KB -> 1 CTA/SM
#define NTHREADS 256

__device__ __forceinline__ void hi8_sts(char* dh, uint32_t so,
                                        const float* __restrict__ src) {
    float4 v0 = *reinterpret_cast<const float4*>(src);
    float4 v1 = *reinterpret_cast<const float4*>(src + 4);
    float xs[8] = {v0.x, v0.y, v0.z, v0.w, v1.x, v1.y, v1.z, v1.w};
    __half h[8];
#pragma unroll
    for (int c = 0; c < 8; c++) h[c] = __float2half(xs[c]);
    *reinterpret_cast<uint4*>(dh + so) = *reinterpret_cast<uint4*>(h);
}

template <int MODE>
struct Cfg {
    static constexpr int STB   = (MODE == 3) ? 49152 : 32768;
    static constexpr int SB    = (MODE == 3) ? 32768 : 16384;
    static constexpr int KTOT  = (MODE == 5) ? 1536
                               : ((MODE == 4 || MODE == 7) ? 1024 : 512);
};

template <int MODE>
__device__ __forceinline__ void load_tileB(uint32_t sbase, int stage,
        const __half* __restrict__ Bh, int n0, int ldb, int kc, int tid) {
    uint32_t dh = sbase + stage * Cfg<MODE>::STB + Cfg<MODE>::SB;
#pragma unroll
    for (int it = 0; it < 4; it++) {               // 128 rows x 8 cols / 256 thr
        int idx = it * NTHREADS + tid;
        int r = idx >> 3, c8 = idx & 7;
        size_t off = (size_t)(n0 + r) * ldb + kc * 64 + c8 * 8;
        uint32_t so = sw128((uint32_t)(r * 128 + c8 * 16));
        cpa16(dh + so, Bh + off);
    }
}

template <int MODE>
__device__ __forceinline__ void load_tileA(char* smem, uint32_t sbase, int stage,
        const __half* __restrict__ Ah, const __half* __restrict__ Al,
        const float* __restrict__ xin, int m0, int lda, int kc, int tid) {
    uint32_t dhu = sbase + stage * Cfg<MODE>::STB;
    uint32_t dlu = dhu + 16384;
    char* dhc = smem + stage * Cfg<MODE>::STB;
#pragma unroll
    for (int it = 0; it < 4; it++) {               // 128 rows x 8 cols / 256 thr
        int idx = it * NTHREADS + tid;
        int r = idx >> 3, c8 = idx & 7;
        uint32_t so = sw128((uint32_t)(r * 128 + c8 * 16));
        if constexpr (MODE <= 2) {
            hi8_sts(dhc, so, &xin[(size_t)(m0 + r) * DD + kc * 64 + c8 * 8]);
        } else if constexpr (MODE == 3) {
            size_t off = (size_t)(m0 + r) * lda + kc * 64 + c8 * 8;
            cpa16(dhu + so, Ah + off);
            cpa16(dlu + so, Al + off);
        } else if constexpr (MODE == 5) {
            int gr = m0 + r, b = gr >> 10, t = gr & 1023;
            int ts = t + (kc >> 3) - 1;
            int ok = ((unsigned)ts < (unsigned)TT) ? 16 : 0;
            int tsc = min(max(ts, 0), TT - 1);
            size_t off = (size_t)((b << 10) + tsc) * DD + (kc & 7) * 64 + c8 * 8;
            cpa16z(dhu + so, g_valh + off, ok);
        } else if constexpr (MODE == 7) {
            int gr = m0 + r;
            if (kc < 8) {
                size_t off = (size_t)gr * DD + kc * 64 + c8 * 8;
                cpa16(dhu + so, g_enhh + off);
            } else {
                hi8_sts(dhc, so, &xin[(size_t)gr * DD + (kc - 8) * 64 + c8 * 8]);
            }
        } else {
            size_t off = (size_t)(m0 + r) * lda + kc * 64 + c8 * 8;
            cpa16(dhu + so, Ah + off);
        }
    }
}

template <int MODE>
__global__ __launch_bounds__(NTHREADS, 2)
void gemm_kernel(const float* __restrict__ bias, const float* __restrict__ xin,
                 const int* __restrict__ vlen, float* __restrict__ fout) {
    constexpr int KT = Cfg<MODE>::KTOT / 64;
    constexpr bool A_DUAL = (MODE == 3);

    extern __shared__ char smem[];
    int tid = threadIdx.x, wid = tid >> 5, lane = tid & 31;
    int bx = blockIdx.x, by = blockIdx.y, bz = blockIdx.z;
    uint32_t sbase = smem_u32_of(smem);
    int m0 = by * 128, n0 = bx * 128;

    const __half *Ah = nullptr, *Al = nullptr, *Bh = nullptr;
    int lda = 512, ldb = 512;
    if constexpr (MODE == 0) { Bh = g_Wqt; }
    if constexpr (MODE == 1) { Bh = g_Wkt; }
    if constexpr (MODE == 2) { Bh = g_Wvt; }
    if constexpr (MODE == 3) {
        size_t bo = (size_t)bz * TT * DD;
        Ah = g_Qh + bo; Al = g_Ql + bo; Bh = g_Kh + bo;
    }
    if constexpr (MODE == 4) {
        Ah = g_Sh + (size_t)bz * TT * TT; lda = 1024;
        Bh = g_Vth + (size_t)bz * DD * TT; ldb = 1024;
    }
    if constexpr (MODE == 5) { Bh = g_Wc1t; ldb = 1536; }
    if constexpr (MODE == 6) { Ah = g_hh; Bh = g_Wc2t; }
    if constexpr (MODE == 7) { Bh = g_Wft; ldb = 1024; }

    // 8 warps: 4 (M) x 2 (N); warp tile 32x64
    int wm = (wid & 3) * 32, wn = (wid >> 2) * 64;
    float acc[2][8][4];
#pragma unroll
    for (int i = 0; i < 2; i++)
#pragma unroll
        for (int j = 0; j < 8; j++)
#pragma unroll
            for (int c = 0; c < 4; c++) acc[i][j][c] = 0.f;

    // prologue: chunks 0,1 -> stages 0,1
    load_tileA<MODE>(smem, sbase, 0, Ah, Al, xin, m0, lda, 0, tid);
    load_tileB<MODE>(sbase, 0, Bh, n0, ldb, 0, tid);
    CP_COMMIT();
    load_tileA<MODE>(smem, sbase, 1, Ah, Al, xin, m0, lda, 1, tid);
    load_tileB<MODE>(sbase, 1, Bh, n0, ldb, 1, tid);
    CP_COMMIT();

    int a_r = (lane & 7) + ((lane >> 3) & 1) * 8;
    int a_c = ((lane >> 4) & 1) * 16;
    int b_r = (lane & 7) + ((lane >> 4) & 1) * 8;
    int b_c = ((lane >> 3) & 1) * 16;

    int cur = 0;
    for (int kt = 0; kt < KT; kt++) {
        if (kt + 1 < KT) CP_WAIT1(); else CP_WAIT0();
        __syncthreads();
        if (kt + 2 < KT) {
            int nxt2 = cur + 2;
            if (nxt2 >= 3) nxt2 -= 3;
            load_tileA<MODE>(smem, sbase, nxt2, Ah, Al, xin, m0, lda, kt + 2, tid);
            load_tileB<MODE>(sbase, nxt2, Bh, n0, ldb, kt + 2, tid);
            CP_COMMIT();
        }
        uint32_t bufa = sbase + cur * Cfg<MODE>::STB;
        uint32_t bufb = bufa + Cfg<MODE>::SB;
#pragma unroll
        for (int ks = 0; ks < 4; ks++) {
            int kb = ks * 32;
            uint32_t ahf[2][4], alf[2][4];
#pragma unroll
            for (int i = 0; i < 2; i++) {
                uint32_t so = sw128((uint32_t)((wm + i * 16 + a_r) * 128 + kb + a_c));
                ldm4(ahf[i], bufa + so);
                if constexpr (A_DUAL) ldm4(alf[i], bufa + 16384 + so);
            }
#pragma unroll
            for (int j2 = 0; j2 < 4; j2++) {
                uint32_t so = sw128((uint32_t)((wn + j2 * 16 + b_r) * 128 + kb + b_c));
                uint32_t tb[4];
                ldm4(tb, bufb + so);
#pragma unroll
                for (int i = 0; i < 2; i++) {
                    MMA_F16(acc[i][2 * j2],     ahf[i], tb[0], tb[1]);
                    MMA_F16(acc[i][2 * j2 + 1], ahf[i], tb[2], tb[3]);
                    if constexpr (A_DUAL) {
                        MMA_F16(acc[i][2 * j2],     alf[i], tb[0], tb[1]);
                        MMA_F16(acc[i][2 * j2 + 1], alf[i], tb[2], tb[3]);
                    }
                }
            }
        }
        cur++;
        if (cur == 3) cur = 0;
    }

    // ---------------- epilogue ----------------
    if constexpr (MODE == 2) {
        // V: stage fp32 in smem, then write V^T (hi plane only)
        __syncthreads();
        float* s = reinterpret_cast<float*>(smem);   // 128 x 132 fp32 = 67584 B
#pragma unroll
        for (int i = 0; i < 2; i++)
#pragma unroll
            for (int j = 0; j < 8; j++) {
                int r0 = wm + i * 16 + (lane >> 2);
                int c = wn + j * 8 + 2 * (lane & 3);
                s[r0 * 132 + c]           = acc[i][j][0] + bias[n0 + c];
                s[r0 * 132 + c + 1]       = acc[i][j][1] + bias[n0 + c + 1];
                s[(r0 + 8) * 132 + c]     = acc[i][j][2] + bias[n0 + c];
                s[(r0 + 8) * 132 + c + 1] = acc[i][j][3] + bias[n0 + c + 1];
            }
        __syncthreads();
        int d = tid & 127;                // head-dim within 128-wide tile
        int mh = (tid >> 7) * 64;         // half of the 128 m-rows
        int b = m0 >> 10, t0 = m0 & 1023;
        size_t obase = ((size_t)b * DD + n0 + d) * TT + t0 + mh;
        for (int m = 0; m < 64; m += 8) {
            __half hb[8];
#pragma unroll
            for (int q = 0; q < 8; q++)
                hb[q] = __float2half(s[(mh + m + q) * 132 + d]);
            *reinterpret_cast<uint4*>(&g_Vth[obase + m]) =
                *reinterpret_cast<uint4*>(hb);
        }
    } else {
#pragma unroll
        for (int i = 0; i < 2; i++)
#pragma unroll
            for (int j = 0; j < 8; j++)
#pragma unroll
                for (int half = 0; half < 2; half++) {
                    int grow = m0 + wm + i * 16 + (lane >> 2) + half * 8;
                    int gcol = n0 + wn + j * 8 + 2 * (lane & 3);
                    float v0 = acc[i][j][half * 2];
                    float v1 = acc[i][j][half * 2 + 1];
                    if constexpr (MODE == 0 || MODE == 1) {
                        v0 += bias[gcol]; v1 += bias[gcol + 1];
                        size_t o = (size_t)grow * DD + gcol;
                        if constexpr (MODE == 0) {
                            uint32_t hp, lp;
                            split_pack(v0, v1, hp, lp);
                            *reinterpret_cast<uint32_t*>(&g_Qh[o]) = hp;
                            *reinterpret_cast<uint32_t*>(&g_Ql[o]) = lp;
                        } else {
                            __half2 hv = {__float2half(v0), __float2half(v1)};
                            *reinterpret_cast<__half2*>(&g_Kh[o]) = hv;
                        }
                    } else if constexpr (MODE == 3) {
                        uint32_t hp, lp;
                        split_pack(v0 * SCALE, v1 * SCALE, hp, lp);
                        size_t o = ((size_t)bz * TT + grow) * TT + gcol;
                        *reinterpret_cast<uint32_t*>(&g_Sh[o]) = hp;
                        *reinterpret_cast<uint32_t*>(&g_Sl[o]) = lp;
                    } else if constexpr (MODE == 4) {
                        size_t o = ((size_t)bz * TT + grow) * DD + gcol;
                        __half2 hv = {__float2half(v0), __float2half(v1)};
                        *reinterpret_cast<__half2*>(&g_valh[o]) = hv;
                    } else if constexpr (MODE == 5) {
                        v0 = fmaxf(v0 + bias[gcol], 0.f);
                        v1 = fmaxf(v1 + bias[gcol + 1], 0.f);
                        size_t o = (size_t)grow * DD + gcol;
                        __half2 hv = {__float2half(v0), __float2half(v1)};
                        *reinterpret_cast<__half2*>(&g_hh[o]) = hv;
                    } else if constexpr (MODE == 6) {
                        int b = grow >> 10, t = grow & 1023;
                        int L = vlen_of(vlen, b);
                        float valid = (t < L) ? 1.f : 0.f;
                        size_t o = (size_t)grow * DD + gcol;
                        float2 a2 = *reinterpret_cast<const float2*>(&xin[o]);
                        float g0 = valid / (1.f + expf(-(v0 + bias[gcol])));
                        float g1 = valid / (1.f + expf(-(v1 + bias[gcol + 1])));
                        __half2 hv = {__float2half(a2.x * g0 + a2.x),
                                      __float2half(a2.y * g1 + a2.y)};
                        *reinterpret_cast<__half2*>(&g_enhh[o]) = hv;
                    } else {  // MODE 7
                        size_t o = (size_t)grow * DD + gcol;
                        float2 r2 = {v0 + bias[gcol], v1 + bias[gcol + 1]};
                        *reinterpret_cast<float2*>(&fout[o]) = r2;
                    }
                }
    }
}

// =================== launch ================================================
extern "C" void kernel_launch(void* const* d_in, const int* in_sizes, int n_in,
                              void* d_out, int out_size) {
    const float* aud = (const float*)d_in[0];
    const float* vid = (const float*)d_in[1];
    const int*   vl  = (const int*)  d_in[2];
    const float* Wq  = (const float*)d_in[3];
    const float* bq  = (const float*)d_in[4];
    const float* Wk  = (const float*)d_in[5];
    const float* bk  = (const float*)d_in[6];
    const float* Wv  = (const float*)d_in[7];
    const float* bv  = (const float*)d_in[8];
    const float* Wc1 = (const float*)d_in[9];
    const float* bc1 = (const float*)d_in[10];
    const float* Wc2 = (const float*)d_in[11];
    const float* bc2 = (const float*)d_in[12];
    const float* Wf  = (const float*)d_in[13];
    const float* bf  = (const float*)d_in[14];
    float* out = (float*)d_out;

    const int SM1 = 3 * 32768;   // 96 KB  (single-A modes; 2 CTAs/SM)
    const int SM3 = 3 * 49152;   // 144 KB (scores, dual-A; 1 CTA/SM)
    cudaFuncSetAttribute(gemm_kernel<0>, cudaFuncAttributeMaxDynamicSharedMemorySize, SM1);
    cudaFuncSetAttribute(gemm_kernel<1>, cudaFuncAttributeMaxDynamicSharedMemorySize, SM1);
    cudaFuncSetAttribute(gemm_kernel<2>, cudaFuncAttributeMaxDynamicSharedMemorySize, SM1);
    cudaFuncSetAttribute(gemm_kernel<3>, cudaFuncAttributeMaxDynamicSharedMemorySize, SM3);
    cudaFuncSetAttribute(gemm_kernel<4>, cudaFuncAttributeMaxDynamicSharedMemorySize, SM1);
    cudaFuncSetAttribute(gemm_kernel<5>, cudaFuncAttributeMaxDynamicSharedMemorySize, SM1);
    cudaFuncSetAttribute(gemm_kernel<6>, cudaFuncAttributeMaxDynamicSharedMemorySize, SM1);
    cudaFuncSetAttribute(gemm_kernel<7>, cudaFuncAttributeMaxDynamicSharedMemorySize, SM1);

    __half *wq, *wk, *wv, *w1, *w2, *wf;
    cudaGetSymbolAddress((void**)&wq, g_Wqt);
    cudaGetSymbolAddress((void**)&wk, g_Wkt);
    cudaGetSymbolAddress((void**)&wv, g_Wvt);
    cudaGetSymbolAddress((void**)&w1, g_Wc1t);
    cudaGetSymbolAddress((void**)&w2, g_Wc2t);
    cudaGetSymbolAddress((void**)&wf, g_Wft);

    wtrans6_kernel<<<dim3(16, 48, 6), 256>>>(Wq, Wk, Wv, Wc1, Wc2, Wf,
                                             wq, wk, wv, w1, w2, wf);

    gemm_kernel<0><<<dim3(4, 128), NTHREADS, SM1>>>(bq, aud, vl, nullptr);
    gemm_kernel<1><<<dim3(4, 128), NTHREADS, SM1>>>(bk, vid, vl, nullptr);
    gemm_kernel<2><<<dim3(4, 128), NTHREADS, SM1>>>(bv, vid, vl, nullptr);
    gemm_kernel<3><<<dim3(8, 8, 16), NTHREADS, SM3>>>(nullptr, nullptr, vl, nullptr);
    softmax_kernel<<<MTOT, 256>>>(vl);
    gemm_kernel<4><<<dim3(4, 8, 16), NTHREADS, SM1>>>(nullptr, nullptr, vl, nullptr);
    gemm_kernel<5><<<dim3(4, 128), NTHREADS, SM1>>>(bc1, nullptr, vl, nullptr);
    gemm_kernel<6><<<dim3(4, 128), NTHREADS, SM1>>>(bc2, aud, vl, nullptr);
    gemm_kernel<7><<<dim3(4, 128), NTHREADS, SM1>>>(bf, vid, vl, out);
}

// round 14
// speedup vs baseline: 1.3511x; 1.3511x over previous
#include <cuda_runtime.h>
#include <cuda_fp16.h>
#include <math.h>
#include <stdint.h>

// Problem constants
#define BB 16
#define TT 1024
#define DD 512
#define MTOT (BB * TT)                  // 16384
#define SCALE 0.04419417382415922f      // 1/sqrt(512)

// =================== helpers (plain sm_80+ features only) ==================
__device__ __forceinline__ uint32_t smem_u32_of(const void* p) {
    uint32_t a;
    asm("{ .reg .u64 t; cvta.to.shared.u64 t, %1; cvt.u32.u64 %0, t; }"
        : "=r"(a) : "l"(p));
    return a;
}
__device__ __forceinline__ void cpa16(uint32_t dst, const void* src) {
    asm volatile("cp.async.cg.shared.global [%0], [%1], 16;"
                 :: "r"(dst), "l"(src));
}
__device__ __forceinline__ void cpa16z(uint32_t dst, const void* src, int sz) {
    asm volatile("cp.async.cg.shared.global [%0], [%1], 16, %2;"
                 :: "r"(dst), "l"(src), "r"(sz));
}
#define CP_COMMIT() asm volatile("cp.async.commit_group;" ::: "memory")
#define CP_WAIT0()  asm volatile("cp.async.wait_group 0;" ::: "memory")
#define CP_WAIT1()  asm volatile("cp.async.wait_group 1;" ::: "memory")

__device__ __forceinline__ void ldm4(uint32_t r[4], uint32_t addr) {
    asm volatile("ldmatrix.sync.aligned.m8n8.x4.shared.b16 {%0,%1,%2,%3}, [%4];"
                 : "=r"(r[0]), "=r"(r[1]), "=r"(r[2]), "=r"(r[3]) : "r"(addr));
}
#define MMA_F16(c, a, b0, b1)                                                  \
    asm volatile("mma.sync.aligned.m16n8k16.row.col.f32.f16.f16.f32 "          \
        "{%0,%1,%2,%3},{%4,%5,%6,%7},{%8,%9},{%0,%1,%2,%3};"                   \
        : "+f"((c)[0]), "+f"((c)[1]), "+f"((c)[2]), "+f"((c)[3])               \
        : "r"((a)[0]), "r"((a)[1]), "r"((a)[2]), "r"((a)[3]),                  \
          "r"(b0), "r"(b1))

__device__ __forceinline__ uint32_t sw128(uint32_t off) {
    return off ^ ((off >> 3) & 0x70);
}

// =================== scratch (fp16; ~151 MB) ===============================
__device__ __half g_Qh[MTOT * DD], g_Ql[MTOT * DD];       // Q pair (scores A)
__device__ __half g_Kh[MTOT * DD];                        // K hi (scores B)
__device__ __half g_Vth[MTOT * DD];                       // V^T hi [b][d][t]
__device__ __half g_Sh[BB * TT * TT], g_Sl[BB * TT * TT]; // logits pair -> probs hi
// dead-buffer aliases (lifetimes verified disjoint)
#define g_valh g_Qh
#define g_hh   g_Kh
#define g_enhh g_Vth
// transposed weights [N, K], hi plane only
__device__ __half g_Wqt[DD * DD];
__device__ __half g_Wkt[DD * DD];
__device__ __half g_Wvt[DD * DD];
__device__ __half g_Wc1t[DD * 1536];
__device__ __half g_Wc2t[DD * DD];
__device__ __half g_Wft[DD * 1024];

__device__ __forceinline__ void split2(float v, __half& h, __half& l) {
    h = __float2half(v);
    l = __float2half(v - __half2float(h));
}
__device__ __forceinline__ void split_pack(float v0, float v1,
                                           uint32_t& hp, uint32_t& lp) {
    __half h0, l0, h1, l1;
    split2(v0, h0, l0);
    split2(v1, h1, l1);
    hp = (uint32_t)__half_as_ushort(h0) | ((uint32_t)__half_as_ushort(h1) << 16);
    lp = (uint32_t)__half_as_ushort(l0) | ((uint32_t)__half_as_ushort(l1) << 16);
}
__device__ __forceinline__ int vlen_of(const int* __restrict__ vl, int b) {
    int stride = (vl[1] == 0) ? 2 : 1;   // int64 vs int32 (values in [1,1024])
    return vl[b * stride];
}

// =================== prep: all 6 weight transposes in one launch ===========
__global__ __launch_bounds__(256)
void wtrans6_kernel(const float* __restrict__ W0, const float* __restrict__ W1,
                    const float* __restrict__ W2, const float* __restrict__ W3,
                    const float* __restrict__ W4, const float* __restrict__ W5,
                    __half* __restrict__ T0, __half* __restrict__ T1,
                    __half* __restrict__ T2, __half* __restrict__ T3,
                    __half* __restrict__ T4, __half* __restrict__ T5) {
    int z = blockIdx.z;
    const float* W = (z == 0) ? W0 : (z == 1) ? W1 : (z == 2) ? W2
                   : (z == 3) ? W3 : (z == 4) ? W4 : W5;
    __half* T = (z == 0) ? T0 : (z == 1) ? T1 : (z == 2) ? T2
              : (z == 3) ? T3 : (z == 4) ? T4 : T5;
    int K = (z == 3) ? 1536 : (z == 5) ? 1024 : 512;
    int k0 = blockIdx.y * 32;
    if (k0 >= K) return;
    __shared__ float t[32][33];
    int n0 = blockIdx.x * 32;
    int tx = threadIdx.x & 31, ty = threadIdx.x >> 5;
    for (int i = ty; i < 32; i += 8)
        t[i][tx] = W[(size_t)(k0 + i) * 512 + n0 + tx];
    __syncthreads();
    for (int i = ty; i < 32; i += 8)
        T[(size_t)(n0 + i) * K + k0 + tx] = __float2half(t[tx][i]);
}

// =================== masked softmax: logits pair -> probs hi ===============
__global__ __launch_bounds__(256)
void softmax_kernel(const int* __restrict__ vl) {
    __shared__ float red[8];
    int row = blockIdx.x;
    int b = row >> 10;
    int L = vlen_of(vl, b);
    size_t rbase = (size_t)row * TT;
    int tid = threadIdx.x, lane = tid & 31, wid = tid >> 5;
    int k0 = tid * 4;
    float xs[4];
#pragma unroll
    for (int c = 0; c < 4; c++)
        xs[c] = __half2float(g_Sh[rbase + k0 + c]) +
                __half2float(g_Sl[rbase + k0 + c]);
    float m = -3.4e38f;
#pragma unroll
    for (int c = 0; c < 4; c++)
        if (k0 + c < L) m = fmaxf(m, xs[c]);
#pragma unroll
    for (int s = 16; s > 0; s >>= 1)
        m = fmaxf(m, __shfl_xor_sync(0xffffffffu, m, s));
    if (lane == 0) red[wid] = m;
    __syncthreads();
    if (wid == 0) {
        float t = red[lane & 7];
#pragma unroll
        for (int s = 4; s > 0; s >>= 1)
            t = fmaxf(t, __shfl_xor_sync(0xffffffffu, t, s));
        if (lane == 0) red[0] = t;
    }
    __syncthreads();
    float rm = red[0];
    float e[4], sum = 0.f;
#pragma unroll
    for (int c = 0; c < 4; c++) {
        e[c] = (k0 + c < L) ? expf(xs[c] - rm) : 0.f;
        sum += e[c];
    }
#pragma unroll
    for (int s = 16; s > 0; s >>= 1)
        sum += __shfl_xor_sync(0xffffffffu, sum, s);
    __syncthreads();
    if (lane == 0) red[wid] = sum;
    __syncthreads();
    if (wid == 0) {
        float t = red[lane & 7];
#pragma unroll
        for (int s = 4; s > 0; s >>= 1)
            t += __shfl_xor_sync(0xffffffffu, t, s);
        if (lane == 0) red[0] = t;
    }
    __syncthreads();
    float inv = 1.f / red[0];
    __half hb[4];
#pragma unroll
    for (int c = 0; c < 4; c++)
        hb[c] = __float2half(e[c] * inv);
    *reinterpret_cast<uint2*>(&g_Sh[rbase + k0]) =
        *reinterpret_cast<uint2*>(hb);
}

// ============ mma.sync GEMM, 128x256 tiles, 512 threads, 3-stage ===========
// MODE: 0=Qproj 1=Kproj 2=Vproj(T out) 3=scores(A dual) 4=PV 5=conv1 6=gate 7=final
// SMEM stage: [Ah 16K][Al 16K][Bh 32K] = 64 KB x3 = 192 KB
#define SA_H 0
#define SA_L 16384
#define SB_H 32768
#define STAGE_BYTES 65536
#define NTHREADS 512

__device__ __forceinline__ void hi8_sts(char* dh, uint32_t so,
                                        const float* __restrict__ src) {
    float4 v0 = *reinterpret_cast<const float4*>(src);
    float4 v1 = *reinterpret_cast<const float4*>(src + 4);
    float xs[8] = {v0.x, v0.y, v0.z, v0.w, v1.x, v1.y, v1.z, v1.w};
    __half h[8];
#pragma unroll
    for (int c = 0; c < 8; c++) h[c] = __float2half(xs[c]);
    *reinterpret_cast<uint4*>(dh + so) = *reinterpret_cast<uint4*>(h);
}

__device__ __forceinline__ void load_tileB(uint32_t sbase, int stage,
        const __half* __restrict__ Bh, int n0, int ldb, int kc, int tid) {
    uint32_t dh = sbase + stage * STAGE_BYTES + SB_H;
#pragma unroll
    for (int it = 0; it < 4; it++) {               // 256 rows x 8 cols / 512 thr
        int idx = it * NTHREADS + tid;
        int r = idx >> 3, c8 = idx & 7;
        size_t off = (size_t)(n0 + r) * ldb + kc * 64 + c8 * 8;
        uint32_t so = sw128((uint32_t)(r * 128 + c8 * 16));
        cpa16(dh + so, Bh + off);
    }
}

template <int MODE>
__device__ __forceinline__ void load_tileA(char* smem, uint32_t sbase, int stage,
        const __half* __restrict__ Ah, const __half* __restrict__ Al,
        const float* __restrict__ xin, int m0, int lda, int kc, int tid) {
    uint32_t dhu = sbase + stage * STAGE_BYTES + SA_H;
    uint32_t dlu = sbase + stage * STAGE_BYTES + SA_L;
    char* dhc = smem + stage * STAGE_BYTES + SA_H;
#pragma unroll
    for (int it = 0; it < 2; it++) {               // 128 rows x 8 cols / 512 thr
        int idx = it * NTHREADS + tid;
        int r = idx >> 3, c8 = idx & 7;
        uint32_t so = sw128((uint32_t)(r * 128 + c8 * 16));
        if constexpr (MODE <= 2) {
            hi8_sts(dhc, so, &xin[(size_t)(m0 + r) * DD + kc * 64 + c8 * 8]);
        } else if constexpr (MODE == 3) {
            size_t off = (size_t)(m0 + r) * lda + kc * 64 + c8 * 8;
            cpa16(dhu + so, Ah + off);
            cpa16(dlu + so, Al + off);
        } else if constexpr (MODE == 5) {
            int gr = m0 + r, b = gr >> 10, t = gr & 1023;
            int ts = t + (kc >> 3) - 1;
            int ok = ((unsigned)ts < (unsigned)TT) ? 16 : 0;
            int tsc = min(max(ts, 0), TT - 1);
            size_t off = (size_t)((b << 10) + tsc) * DD + (kc & 7) * 64 + c8 * 8;
            cpa16z(dhu + so, g_valh + off, ok);
        } else if constexpr (MODE == 7) {
            int gr = m0 + r;
            if (kc < 8) {
                size_t off = (size_t)gr * DD + kc * 64 + c8 * 8;
                cpa16(dhu + so, g_enhh + off);
            } else {
                hi8_sts(dhc, so, &xin[(size_t)gr * DD + (kc - 8) * 64 + c8 * 8]);
            }
        } else {
            size_t off = (size_t)(m0 + r) * lda + kc * 64 + c8 * 8;
            cpa16(dhu + so, Ah + off);
        }
    }
}

template <int MODE>
__global__ __launch_bounds__(NTHREADS)
void gemm_kernel(const float* __restrict__ bias, const float* __restrict__ xin,
                 const int* __restrict__ vlen, float* __restrict__ fout) {
    constexpr int KTOT = (MODE == 5) ? 1536 : ((MODE == 4 || MODE == 7) ? 1024 : 512);
    constexpr int KT = KTOT / 64;
    constexpr bool A_DUAL = (MODE == 3);

    extern __shared__ char smem[];
    int tid = threadIdx.x, wid = tid >> 5, lane = tid & 31;
    int bx = blockIdx.x, by = blockIdx.y, bz = blockIdx.z;
    uint32_t sbase = smem_u32_of(smem);
    int m0 = by * 128, n0 = bx * 256;

    // ---- mask-based CTA skips (bit-exact: removed work is exactly zero /
    //      exactly discarded downstream) ----
    int ktEnd = KT;
    if constexpr (MODE == 3) {
        int L = vlen_of(vlen, bz);
        if (n0 >= L) return;             // keys all masked by softmax
    }
    if constexpr (MODE == 4) {
        int L = vlen_of(vlen, bz);
        if (m0 > L) return;              // value[t] unused for t > L
        ktEnd = min(KT, (L + 63) >> 6);  // P cols >= L are exact zeros
    }
    if constexpr (MODE == 5) {
        int L = vlen_of(vlen, m0 >> 10);
        if ((m0 & 1023) >= L) return;    // h[t] gated to zero for t >= L
    }

    const __half *Ah = nullptr, *Al = nullptr, *Bh = nullptr;
    int lda = 512, ldb = 512;
    if constexpr (MODE == 0) { Bh = g_Wqt; }
    if constexpr (MODE == 1) { Bh = g_Wkt; }
    if constexpr (MODE == 2) { Bh = g_Wvt; }
    if constexpr (MODE == 3) {
        size_t bo = (size_t)bz * TT * DD;
        Ah = g_Qh + bo; Al = g_Ql + bo; Bh = g_Kh + bo;
    }
    if constexpr (MODE == 4) {
        Ah = g_Sh + (size_t)bz * TT * TT; lda = 1024;
        Bh = g_Vth + (size_t)bz * DD * TT; ldb = 1024;
    }
    if constexpr (MODE == 5) { Bh = g_Wc1t; ldb = 1536; }
    if constexpr (MODE == 6) { Ah = g_hh; Bh = g_Wc2t; }
    if constexpr (MODE == 7) { Bh = g_Wft; ldb = 1024; }

    // 16 warps: 4 (M) x 4 (N); warp tile 32x64
    int wm = (wid & 3) * 32, wn = (wid >> 2) * 64;
    float acc[2][8][4];
#pragma unroll
    for (int i = 0; i < 2; i++)
#pragma unroll
        for (int j = 0; j < 8; j++)
#pragma unroll
            for (int c = 0; c < 4; c++) acc[i][j][c] = 0.f;

    // prologue: chunks 0,1 -> stages 0,1 (chunk 1 may be past ktEnd; loads
    // stay in-bounds and are simply unused)
    load_tileA<MODE>(smem, sbase, 0, Ah, Al, xin, m0, lda, 0, tid);
    load_tileB(sbase, 0, Bh, n0, ldb, 0, tid);
    CP_COMMIT();
    load_tileA<MODE>(smem, sbase, 1, Ah, Al, xin, m0, lda, 1, tid);
    load_tileB(sbase, 1, Bh, n0, ldb, 1, tid);
    CP_COMMIT();

    int a_r = (lane & 7) + ((lane >> 3) & 1) * 8;
    int a_c = ((lane >> 4) & 1) * 16;
    int b_r = (lane & 7) + ((lane >> 4) & 1) * 8;
    int b_c = ((lane >> 3) & 1) * 16;

    int cur = 0;
    for (int kt = 0; kt < ktEnd; kt++) {
        if (kt + 1 < ktEnd) CP_WAIT1(); else CP_WAIT0();
        __syncthreads();
        if (kt + 2 < ktEnd) {
            int nxt2 = cur + 2;
            if (nxt2 >= 3) nxt2 -= 3;
            load_tileA<MODE>(smem, sbase, nxt2, Ah, Al, xin, m0, lda, kt + 2, tid);
            load_tileB(sbase, nxt2, Bh, n0, ldb, kt + 2, tid);
            CP_COMMIT();
        }
        uint32_t bufb = sbase + cur * STAGE_BYTES;
#pragma unroll
        for (int ks = 0; ks < 4; ks++) {
            int kb = ks * 32;
            uint32_t ahf[2][4], alf[2][4];
#pragma unroll
            for (int i = 0; i < 2; i++) {
                uint32_t so = sw128((uint32_t)((wm + i * 16 + a_r) * 128 + kb + a_c));
                ldm4(ahf[i], bufb + SA_H + so);
                if constexpr (A_DUAL) ldm4(alf[i], bufb + SA_L + so);
            }
#pragma unroll
            for (int j2 = 0; j2 < 4; j2++) {
                uint32_t so = sw128((uint32_t)((wn + j2 * 16 + b_r) * 128 + kb + b_c));
                uint32_t tb[4];
                ldm4(tb, bufb + SB_H + so);
#pragma unroll
                for (int i = 0; i < 2; i++) {
                    MMA_F16(acc[i][2 * j2],     ahf[i], tb[0], tb[1]);
                    MMA_F16(acc[i][2 * j2 + 1], ahf[i], tb[2], tb[3]);
                    if constexpr (A_DUAL) {
                        MMA_F16(acc[i][2 * j2],     alf[i], tb[0], tb[1]);
                        MMA_F16(acc[i][2 * j2 + 1], alf[i], tb[2], tb[3]);
                    }
                }
            }
        }
        cur++;
        if (cur == 3) cur = 0;
    }

    // ---------------- epilogue ----------------
    if constexpr (MODE == 2) {
        // V: stage fp32 in smem, then write V^T (hi plane only)
        __syncthreads();
        float* s = reinterpret_cast<float*>(smem);   // 128 x 264 fp32 = 135168 B
#pragma unroll
        for (int i = 0; i < 2; i++)
#pragma unroll
            for (int j = 0; j < 8; j++) {
                int r0 = wm + i * 16 + (lane >> 2);
                int c = wn + j * 8 + 2 * (lane & 3);
                s[r0 * 264 + c]           = acc[i][j][0] + bias[n0 + c];
                s[r0 * 264 + c + 1]       = acc[i][j][1] + bias[n0 + c + 1];
                s[(r0 + 8) * 264 + c]     = acc[i][j][2] + bias[n0 + c];
                s[(r0 + 8) * 264 + c + 1] = acc[i][j][3] + bias[n0 + c + 1];
            }
        __syncthreads();
        int d = tid & 255;                // head-dim within tile
        int mh = (tid >> 8) * 64;         // half of the 128 m-rows
        int b = m0 >> 10, t0 = m0 & 1023;
        size_t obase = ((size_t)b * DD + n0 + d) * TT + t0 + mh;
        for (int m = 0; m < 64; m += 8) {
            __half hb[8];
#pragma unroll
            for (int q = 0; q < 8; q++)
                hb[q] = __float2half(s[(mh + m + q) * 264 + d]);
            *reinterpret_cast<uint4*>(&g_Vth[obase + m]) =
                *reinterpret_cast<uint4*>(hb);
        }
    } else {
#pragma unroll
        for (int i = 0; i < 2; i++)
#pragma unroll
            for (int j = 0; j < 8; j++)
#pragma unroll
                for (int half = 0; half < 2; half++) {
                    int grow = m0 + wm + i * 16 + (lane >> 2) + half * 8;
                    int gcol = n0 + wn + j * 8 + 2 * (lane & 3);
                    float v0 = acc[i][j][half * 2];
                    float v1 = acc[i][j][half * 2 + 1];
                    if constexpr (MODE == 0 || MODE == 1) {
                        v0 += bias[gcol]; v1 += bias[gcol + 1];
                        size_t o = (size_t)grow * DD + gcol;
                        if constexpr (MODE == 0) {
                            uint32_t hp, lp;
                            split_pack(v0, v1, hp, lp);
                            *reinterpret_cast<uint32_t*>(&g_Qh[o]) = hp;
                            *reinterpret_cast<uint32_t*>(&g_Ql[o]) = lp;
                        } else {
                            __half2 hv = {__float2half(v0), __float2half(v1)};
                            *reinterpret_cast<__half2*>(&g_Kh[o]) = hv;
                        }
                    } else if constexpr (MODE == 3) {
                        uint32_t hp, lp;
                        split_pack(v0 * SCALE, v1 * SCALE, hp, lp);
                        size_t o = ((size_t)bz * TT + grow) * TT + gcol;
                        *reinterpret_cast<uint32_t*>(&g_Sh[o]) = hp;
                        *reinterpret_cast<uint32_t*>(&g_Sl[o]) = lp;
                    } else if constexpr (MODE == 4) {
                        size_t o = ((size_t)bz * TT + grow) * DD + gcol;
                        __half2 hv = {__float2half(v0), __float2half(v1)};
                        *reinterpret_cast<__half2*>(&g_valh[o]) = hv;
                    } else if constexpr (MODE == 5) {
                        v0 = fmaxf(v0 + bias[gcol], 0.f);
                        v1 = fmaxf(v1 + bias[gcol + 1], 0.f);
                        size_t o = (size_t)grow * DD + gcol;
                        __half2 hv = {__float2half(v0), __float2half(v1)};
                        *reinterpret_cast<__half2*>(&g_hh[o]) = hv;
                    } else if constexpr (MODE == 6) {
                        int b = grow >> 10, t = grow & 1023;
                        int L = vlen_of(vlen, b);
                        float valid = (t < L) ? 1.f : 0.f;
                        size_t o = (size_t)grow * DD + gcol;
                        float2 a2 = *reinterpret_cast<const float2*>(&xin[o]);
                        float g0 = valid / (1.f + expf(-(v0 + bias[gcol])));
                        float g1 = valid / (1.f + expf(-(v1 + bias[gcol + 1])));
                        __half2 hv = {__float2half(a2.x * g0 + a2.x),
                                      __float2half(a2.y * g1 + a2.y)};
                        *reinterpret_cast<__half2*>(&g_enhh[o]) = hv;
                    } else {  // MODE 7
                        size_t o = (size_t)grow * DD + gcol;
                        float2 r2 = {v0 + bias[gcol], v1 + bias[gcol + 1]};
                        *reinterpret_cast<float2*>(&fout[o]) = r2;
                    }
                }
    }
}

// =================== launch ================================================
extern "C" void kernel_launch(void* const* d_in, const int* in_sizes, int n_in,
                              void* d_out, int out_size) {
    const float* aud = (const float*)d_in[0];
    const float* vid = (const float*)d_in[1];
    const int*   vl  = (const int*)  d_in[2];
    const float* Wq  = (const float*)d_in[3];
    const float* bq  = (const float*)d_in[4];
    const float* Wk  = (const float*)d_in[5];
    const float* bk  = (const float*)d_in[6];
    const float* Wv  = (const float*)d_in[7];
    const float* bv  = (const float*)d_in[8];
    const float* Wc1 = (const float*)d_in[9];
    const float* bc1 = (const float*)d_in[10];
    const float* Wc2 = (const float*)d_in[11];
    const float* bc2 = (const float*)d_in[12];
    const float* Wf  = (const float*)d_in[13];
    const float* bf  = (const float*)d_in[14];
    float* out = (float*)d_out;

    const int SM = 196608;   // 3 stages x 64 KB
    cudaFuncSetAttribute(gemm_kernel<0>, cudaFuncAttributeMaxDynamicSharedMemorySize, SM);
    cudaFuncSetAttribute(gemm_kernel<1>, cudaFuncAttributeMaxDynamicSharedMemorySize, SM);
    cudaFuncSetAttribute(gemm_kernel<2>, cudaFuncAttributeMaxDynamicSharedMemorySize, SM);
    cudaFuncSetAttribute(gemm_kernel<3>, cudaFuncAttributeMaxDynamicSharedMemorySize, SM);
    cudaFuncSetAttribute(gemm_kernel<4>, cudaFuncAttributeMaxDynamicSharedMemorySize, SM);
    cudaFuncSetAttribute(gemm_kernel<5>, cudaFuncAttributeMaxDynamicSharedMemorySize, SM);
    cudaFuncSetAttribute(gemm_kernel<6>, cudaFuncAttributeMaxDynamicSharedMemorySize, SM);
    cudaFuncSetAttribute(gemm_kernel<7>, cudaFuncAttributeMaxDynamicSharedMemorySize, SM);

    __half *wq, *wk, *wv, *w1, *w2, *wf;
    cudaGetSymbolAddress((void**)&wq, g_Wqt);
    cudaGetSymbolAddress((void**)&wk, g_Wkt);
    cudaGetSymbolAddress((void**)&wv, g_Wvt);
    cudaGetSymbolAddress((void**)&w1, g_Wc1t);
    cudaGetSymbolAddress((void**)&w2, g_Wc2t);
    cudaGetSymbolAddress((void**)&wf, g_Wft);

    wtrans6_kernel<<<dim3(16, 48, 6), 256>>>(Wq, Wk, Wv, Wc1, Wc2, Wf,
                                             wq, wk, wv, w1, w2, wf);

    gemm_kernel<0><<<dim3(2, 128), NTHREADS, SM>>>(bq, aud, vl, nullptr);
    gemm_kernel<1><<<dim3(2, 128), NTHREADS, SM>>>(bk, vid, vl, nullptr);
    gemm_kernel<2><<<dim3(2, 128), NTHREADS, SM>>>(bv, vid, vl, nullptr);
    gemm_kernel<3><<<dim3(4, 8, 16), NTHREADS, SM>>>(nullptr, nullptr, vl, nullptr);
    softmax_kernel<<<MTOT, 256>>>(vl);
    gemm_kernel<4><<<dim3(2, 8, 16), NTHREADS, SM>>>(nullptr, nullptr, vl, nullptr);
    gemm_kernel<5><<<dim3(2, 128), NTHREADS, SM>>>(bc1, nullptr, vl, nullptr);
    gemm_kernel<6><<<dim3(2, 128), NTHREADS, SM>>>(bc2, aud, vl, nullptr);
    gemm_kernel<7><<<dim3(2, 128), NTHREADS, SM>>>(bf, vid, vl, out);
}

// round 15
// speedup vs baseline: 1.4705x; 1.0884x over previous
#include <cuda_runtime.h>
#include <cuda_fp16.h>
#include <math.h>
#include <stdint.h>

// Problem constants
#define BB 16
#define TT 1024
#define DD 512
#define MTOT (BB * TT)                  // 16384
#define SCALE 0.04419417382415922f      // 1/sqrt(512)

// =================== helpers (plain sm_80+ features only) ==================
__device__ __forceinline__ uint32_t smem_u32_of(const void* p) {
    uint32_t a;
    asm("{ .reg .u64 t; cvta.to.shared.u64 t, %1; cvt.u32.u64 %0, t; }"
        : "=r"(a) : "l"(p));
    return a;
}
__device__ __forceinline__ void cpa16(uint32_t dst, const void* src) {
    asm volatile("cp.async.cg.shared.global [%0], [%1], 16;"
                 :: "r"(dst), "l"(src));
}
__device__ __forceinline__ void cpa16z(uint32_t dst, const void* src, int sz) {
    asm volatile("cp.async.cg.shared.global [%0], [%1], 16, %2;"
                 :: "r"(dst), "l"(src), "r"(sz));
}
#define CP_COMMIT() asm volatile("cp.async.commit_group;" ::: "memory")
#define CP_WAIT0()  asm volatile("cp.async.wait_group 0;" ::: "memory")
#define CP_WAIT1()  asm volatile("cp.async.wait_group 1;" ::: "memory")

__device__ __forceinline__ void ldm4(uint32_t r[4], uint32_t addr) {
    asm volatile("ldmatrix.sync.aligned.m8n8.x4.shared.b16 {%0,%1,%2,%3}, [%4];"
                 : "=r"(r[0]), "=r"(r[1]), "=r"(r[2]), "=r"(r[3]) : "r"(addr));
}
#define MMA_F16(c, a, b0, b1)                                                  \
    asm volatile("mma.sync.aligned.m16n8k16.row.col.f32.f16.f16.f32 "          \
        "{%0,%1,%2,%3},{%4,%5,%6,%7},{%8,%9},{%0,%1,%2,%3};"                   \
        : "+f"((c)[0]), "+f"((c)[1]), "+f"((c)[2]), "+f"((c)[3])               \
        : "r"((a)[0]), "r"((a)[1]), "r"((a)[2]), "r"((a)[3]),                  \
          "r"(b0), "r"(b1))

__device__ __forceinline__ uint32_t sw128(uint32_t off) {
    return off ^ ((off >> 3) & 0x70);
}

// =================== scratch (fp16; ~183 MB) ===============================
__device__ __half g_audh[MTOT * DD];                      // aud fp16 hi
__device__ __half g_vidh[MTOT * DD];                      // vid fp16 hi
__device__ __half g_Qh[MTOT * DD], g_Ql[MTOT * DD];       // Q pair (scores A)
__device__ __half g_Kh[MTOT * DD];                        // K hi (scores B)
__device__ __half g_Vth[MTOT * DD];                       // V^T hi [b][d][t]
__device__ __half g_Sh[BB * TT * TT], g_Sl[BB * TT * TT]; // logits pair -> probs hi
// dead-buffer aliases (lifetimes verified disjoint)
#define g_valh g_Qh
#define g_hh   g_Kh
#define g_enhh g_Vth
// transposed weights [N, K], hi plane only
__device__ __half g_Wqt[DD * DD];
__device__ __half g_Wkt[DD * DD];
__device__ __half g_Wvt[DD * DD];
__device__ __half g_Wc1t[DD * 1536];
__device__ __half g_Wc2t[DD * DD];
__device__ __half g_Wft[DD * 1024];

__device__ __forceinline__ void split2(float v, __half& h, __half& l) {
    h = __float2half(v);
    l = __float2half(v - __half2float(h));
}
__device__ __forceinline__ void split_pack(float v0, float v1,
                                           uint32_t& hp, uint32_t& lp) {
    __half h0, l0, h1, l1;
    split2(v0, h0, l0);
    split2(v1, h1, l1);
    hp = (uint32_t)__half_as_ushort(h0) | ((uint32_t)__half_as_ushort(h1) << 16);
    lp = (uint32_t)__half_as_ushort(l0) | ((uint32_t)__half_as_ushort(l1) << 16);
}
__device__ __forceinline__ int vlen_of(const int* __restrict__ vl, int b) {
    int stride = (vl[1] == 0) ? 2 : 1;   // int64 vs int32 (values in [1,1024])
    return vl[b * stride];
}

// =================== prep: fp32 -> fp16 hi conversion ======================
__global__ __launch_bounds__(256)
void cvt_kernel(const float* __restrict__ X, __half* __restrict__ Y) {
    int i = (blockIdx.x * 256 + threadIdx.x) * 8;
    float4 v0 = *reinterpret_cast<const float4*>(X + i);
    float4 v1 = *reinterpret_cast<const float4*>(X + i + 4);
    float xs[8] = {v0.x, v0.y, v0.z, v0.w, v1.x, v1.y, v1.z, v1.w};
    __half h[8];
#pragma unroll
    for (int c = 0; c < 8; c++) h[c] = __float2half(xs[c]);
    *reinterpret_cast<uint4*>(Y + i) = *reinterpret_cast<uint4*>(h);
}

// =================== prep: all 6 weight transposes in one launch ===========
__global__ __launch_bounds__(256)
void wtrans6_kernel(const float* __restrict__ W0, const float* __restrict__ W1,
                    const float* __restrict__ W2, const float* __restrict__ W3,
                    const float* __restrict__ W4, const float* __restrict__ W5,
                    __half* __restrict__ T0, __half* __restrict__ T1,
                    __half* __restrict__ T2, __half* __restrict__ T3,
                    __half* __restrict__ T4, __half* __restrict__ T5) {
    int z = blockIdx.z;
    const float* W = (z == 0) ? W0 : (z == 1) ? W1 : (z == 2) ? W2
                   : (z == 3) ? W3 : (z == 4) ? W4 : W5;
    __half* T = (z == 0) ? T0 : (z == 1) ? T1 : (z == 2) ? T2
              : (z == 3) ? T3 : (z == 4) ? T4 : T5;
    int K = (z == 3) ? 1536 : (z == 5) ? 1024 : 512;
    int k0 = blockIdx.y * 32;
    if (k0 >= K) return;
    __shared__ float t[32][33];
    int n0 = blockIdx.x * 32;
    int tx = threadIdx.x & 31, ty = threadIdx.x >> 5;
    for (int i = ty; i < 32; i += 8)
        t[i][tx] = W[(size_t)(k0 + i) * 512 + n0 + tx];
    __syncthreads();
    for (int i = ty; i < 32; i += 8)
        T[(size_t)(n0 + i) * K + k0 + tx] = __float2half(t[tx][i]);
}

// =================== masked softmax: logits pair -> probs hi ===============
__global__ __launch_bounds__(256)
void softmax_kernel(const int* __restrict__ vl) {
    __shared__ float red[8];
    int row = blockIdx.x;
    int b = row >> 10;
    int L = vlen_of(vl, b);
    int Lc = (L + 63) & ~63;            // PV reads cols < ceil64(L) only
    size_t rbase = (size_t)row * TT;
    int tid = threadIdx.x, lane = tid & 31, wid = tid >> 5;
    int k0 = tid * 4;
    float xs[4];
    if (k0 < L) {
#pragma unroll
        for (int c = 0; c < 4; c++)
            xs[c] = __half2float(g_Sh[rbase + k0 + c]) +
                    __half2float(g_Sl[rbase + k0 + c]);
    } else {
#pragma unroll
        for (int c = 0; c < 4; c++) xs[c] = -3.4e38f;
    }
    float m = -3.4e38f;
#pragma unroll
    for (int c = 0; c < 4; c++)
        if (k0 + c < L) m = fmaxf(m, xs[c]);
#pragma unroll
    for (int s = 16; s > 0; s >>= 1)
        m = fmaxf(m, __shfl_xor_sync(0xffffffffu, m, s));
    if (lane == 0) red[wid] = m;
    __syncthreads();
    if (wid == 0) {
        float t = red[lane & 7];
#pragma unroll
        for (int s = 4; s > 0; s >>= 1)
            t = fmaxf(t, __shfl_xor_sync(0xffffffffu, t, s));
        if (lane == 0) red[0] = t;
    }
    __syncthreads();
    float rm = red[0];
    float e[4], sum = 0.f;
#pragma unroll
    for (int c = 0; c < 4; c++) {
        e[c] = (k0 + c < L) ? expf(xs[c] - rm) : 0.f;
        sum += e[c];
    }
#pragma unroll
    for (int s = 16; s > 0; s >>= 1)
        sum += __shfl_xor_sync(0xffffffffu, sum, s);
    __syncthreads();
    if (lane == 0) red[wid] = sum;
    __syncthreads();
    if (wid == 0) {
        float t = red[lane & 7];
#pragma unroll
        for (int s = 4; s > 0; s >>= 1)
            t += __shfl_xor_sync(0xffffffffu, t, s);
        if (lane == 0) red[0] = t;
    }
    __syncthreads();
    if (k0 < Lc) {
        float inv = 1.f / red[0];
        __half hb[4];
#pragma unroll
        for (int c = 0; c < 4; c++)
            hb[c] = __float2half(e[c] * inv);
        *reinterpret_cast<uint2*>(&g_Sh[rbase + k0]) =
            *reinterpret_cast<uint2*>(hb);
    }
}

// ============ mma.sync GEMM, 128x256 tiles, 512 threads, 3-stage ===========
// MODE: 0=QKVproj(bz sel) 3=scores(A dual) 4=PV 5=conv1 6=gate 7=final
// SMEM stage: [Ah 16K][Al 16K][Bh 32K] = 64 KB x3 = 192 KB
#define SA_H 0
#define SA_L 16384
#define SB_H 32768
#define STAGE_BYTES 65536
#define NTHREADS 512

__device__ __forceinline__ void load_tileB(uint32_t sbase, int stage,
        const __half* __restrict__ Bh, int n0, int ldb, int kc, int tid) {
    uint32_t dh = sbase + stage * STAGE_BYTES + SB_H;
#pragma unroll
    for (int it = 0; it < 4; it++) {               // 256 rows x 8 cols / 512 thr
        int idx = it * NTHREADS + tid;
        int r = idx >> 3, c8 = idx & 7;
        size_t off = (size_t)(n0 + r) * ldb + kc * 64 + c8 * 8;
        uint32_t so = sw128((uint32_t)(r * 128 + c8 * 16));
        cpa16(dh + so, Bh + off);
    }
}

template <int MODE>
__device__ __forceinline__ void load_tileA(uint32_t sbase, int stage,
        const __half* __restrict__ Ah, const __half* __restrict__ Al,
        int m0, int lda, int kc, int tid) {
    uint32_t dhu = sbase + stage * STAGE_BYTES + SA_H;
    uint32_t dlu = sbase + stage * STAGE_BYTES + SA_L;
#pragma unroll
    for (int it = 0; it < 2; it++) {               // 128 rows x 8 cols / 512 thr
        int idx = it * NTHREADS + tid;
        int r = idx >> 3, c8 = idx & 7;
        uint32_t so = sw128((uint32_t)(r * 128 + c8 * 16));
        if constexpr (MODE == 3) {
            size_t off = (size_t)(m0 + r) * lda + kc * 64 + c8 * 8;
            cpa16(dhu + so, Ah + off);
            cpa16(dlu + so, Al + off);
        } else if constexpr (MODE == 5) {
            int gr = m0 + r, b = gr >> 10, t = gr & 1023;
            int ts = t + (kc >> 3) - 1;
            int ok = ((unsigned)ts < (unsigned)TT) ? 16 : 0;
            int tsc = min(max(ts, 0), TT - 1);
            size_t off = (size_t)((b << 10) + tsc) * DD + (kc & 7) * 64 + c8 * 8;
            cpa16z(dhu + so, g_valh + off, ok);
        } else if constexpr (MODE == 7) {
            int gr = m0 + r;
            const __half* src = (kc < 8) ? g_enhh : g_vidh;
            int kk = (kc < 8) ? kc : (kc - 8);
            size_t off = (size_t)gr * DD + kk * 64 + c8 * 8;
            cpa16(dhu + so, src + off);
        } else {
            // MODE 0 (audh/vidh), MODE 4 (P hi), MODE 6 (h hi)
            size_t off = (size_t)(m0 + r) * lda + kc * 64 + c8 * 8;
            cpa16(dhu + so, Ah + off);
        }
    }
}

template <int MODE>
__global__ __launch_bounds__(NTHREADS)
void gemm_kernel(const float* __restrict__ bias, const float* __restrict__ xin,
                 const int* __restrict__ vlen, float* __restrict__ fout,
                 const float* __restrict__ bias1, const float* __restrict__ bias2) {
    constexpr int KTOT = (MODE == 5) ? 1536 : ((MODE == 4 || MODE == 7) ? 1024 : 512);
    constexpr int KT = KTOT / 64;
    constexpr bool A_DUAL = (MODE == 3);

    extern __shared__ char smem[];
    int tid = threadIdx.x, wid = tid >> 5, lane = tid & 31;
    int bx = blockIdx.x, by = blockIdx.y, bz = blockIdx.z;
    uint32_t sbase = smem_u32_of(smem);
    int m0 = by * 128, n0 = bx * 256;

    // ---- mask-based CTA skips (bit-exact) ----
    int ktEnd = KT;
    if constexpr (MODE == 3) {
        int L = vlen_of(vlen, bz);
        if (n0 >= L) return;             // keys all masked by softmax
    }
    if constexpr (MODE == 4) {
        int L = vlen_of(vlen, bz);
        if (m0 > L) return;              // value[t] unused for t > L
        ktEnd = min(KT, (L + 63) >> 6);  // P cols >= L are exact zeros
    }
    if constexpr (MODE == 5) {
        int L = vlen_of(vlen, m0 >> 10);
        if ((m0 & 1023) >= L) return;    // h[t] gated to zero for t >= L
    }

    const __half *Ah = nullptr, *Al = nullptr, *Bh = nullptr;
    const float* bvec = bias;
    int lda = 512, ldb = 512;
    if constexpr (MODE == 0) {
        // bz: 0=Q(aud,Wq) 1=K(vid,Wk) 2=V(vid,Wv)
        Ah = (bz == 0) ? g_audh : g_vidh;
        Bh = (bz == 0) ? g_Wqt : (bz == 1) ? g_Wkt : g_Wvt;
        bvec = (bz == 0) ? bias : (bz == 1) ? bias1 : bias2;
    }
    if constexpr (MODE == 3) {
        size_t bo = (size_t)bz * TT * DD;
        Ah = g_Qh + bo; Al = g_Ql + bo; Bh = g_Kh + bo;
    }
    if constexpr (MODE == 4) {
        Ah = g_Sh + (size_t)bz * TT * TT; lda = 1024;
        Bh = g_Vth + (size_t)bz * DD * TT; ldb = 1024;
    }
    if constexpr (MODE == 5) { Bh = g_Wc1t; ldb = 1536; }
    if constexpr (MODE == 6) { Ah = g_hh; Bh = g_Wc2t; }
    if constexpr (MODE == 7) { Bh = g_Wft; ldb = 1024; }

    // 16 warps: 4 (M) x 4 (N); warp tile 32x64
    int wm = (wid & 3) * 32, wn = (wid >> 2) * 64;
    float acc[2][8][4];
#pragma unroll
    for (int i = 0; i < 2; i++)
#pragma unroll
        for (int j = 0; j < 8; j++)
#pragma unroll
            for (int c = 0; c < 4; c++) acc[i][j][c] = 0.f;

    // prologue: chunks 0,1 -> stages 0,1
    load_tileA<MODE>(sbase, 0, Ah, Al, m0, lda, 0, tid);
    load_tileB(sbase, 0, Bh, n0, ldb, 0, tid);
    CP_COMMIT();
    load_tileA<MODE>(sbase, 1, Ah, Al, m0, lda, 1, tid);
    load_tileB(sbase, 1, Bh, n0, ldb, 1, tid);
    CP_COMMIT();

    int a_r = (lane & 7) + ((lane >> 3) & 1) * 8;
    int a_c = ((lane >> 4) & 1) * 16;
    int b_r = (lane & 7) + ((lane >> 4) & 1) * 8;
    int b_c = ((lane >> 3) & 1) * 16;

    int cur = 0;
    for (int kt = 0; kt < ktEnd; kt++) {
        if (kt + 1 < ktEnd) CP_WAIT1(); else CP_WAIT0();
        __syncthreads();
        if (kt + 2 < ktEnd) {
            int nxt2 = cur + 2;
            if (nxt2 >= 3) nxt2 -= 3;
            load_tileA<MODE>(sbase, nxt2, Ah, Al, m0, lda, kt + 2, tid);
            load_tileB(sbase, nxt2, Bh, n0, ldb, kt + 2, tid);
            CP_COMMIT();
        }
        uint32_t bufb = sbase + cur * STAGE_BYTES;
#pragma unroll
        for (int ks = 0; ks < 4; ks++) {
            int kb = ks * 32;
            uint32_t ahf[2][4], alf[2][4];
#pragma unroll
            for (int i = 0; i < 2; i++) {
                uint32_t so = sw128((uint32_t)((wm + i * 16 + a_r) * 128 + kb + a_c));
                ldm4(ahf[i], bufb + SA_H + so);
                if constexpr (A_DUAL) ldm4(alf[i], bufb + SA_L + so);
            }
#pragma unroll
            for (int j2 = 0; j2 < 4; j2++) {
                uint32_t so = sw128((uint32_t)((wn + j2 * 16 + b_r) * 128 + kb + b_c));
                uint32_t tb[4];
                ldm4(tb, bufb + SB_H + so);
#pragma unroll
                for (int i = 0; i < 2; i++) {
                    MMA_F16(acc[i][2 * j2],     ahf[i], tb[0], tb[1]);
                    MMA_F16(acc[i][2 * j2 + 1], ahf[i], tb[2], tb[3]);
                    if constexpr (A_DUAL) {
                        MMA_F16(acc[i][2 * j2],     alf[i], tb[0], tb[1]);
                        MMA_F16(acc[i][2 * j2 + 1], alf[i], tb[2], tb[3]);
                    }
                }
            }
        }
        cur++;
        if (cur == 3) cur = 0;
    }

    // ---------------- epilogue ----------------
    if constexpr (MODE == 0) {
        if (bz == 2) {
            // V: stage fp32 in smem, then write V^T (hi plane only)
            __syncthreads();
            float* s = reinterpret_cast<float*>(smem);   // 128 x 264 fp32
#pragma unroll
            for (int i = 0; i < 2; i++)
#pragma unroll
                for (int j = 0; j < 8; j++) {
                    int r0 = wm + i * 16 + (lane >> 2);
                    int c = wn + j * 8 + 2 * (lane & 3);
                    s[r0 * 264 + c]           = acc[i][j][0] + bvec[n0 + c];
                    s[r0 * 264 + c + 1]       = acc[i][j][1] + bvec[n0 + c + 1];
                    s[(r0 + 8) * 264 + c]     = acc[i][j][2] + bvec[n0 + c];
                    s[(r0 + 8) * 264 + c + 1] = acc[i][j][3] + bvec[n0 + c + 1];
                }
            __syncthreads();
            int d = tid & 255;
            int mh = (tid >> 8) * 64;
            int b = m0 >> 10, t0 = m0 & 1023;
            size_t obase = ((size_t)b * DD + n0 + d) * TT + t0 + mh;
            for (int m = 0; m < 64; m += 8) {
                __half hb[8];
#pragma unroll
                for (int q = 0; q < 8; q++)
                    hb[q] = __float2half(s[(mh + m + q) * 264 + d]);
                *reinterpret_cast<uint4*>(&g_Vth[obase + m]) =
                    *reinterpret_cast<uint4*>(hb);
            }
        } else {
#pragma unroll
            for (int i = 0; i < 2; i++)
#pragma unroll
                for (int j = 0; j < 8; j++)
#pragma unroll
                    for (int half = 0; half < 2; half++) {
                        int grow = m0 + wm + i * 16 + (lane >> 2) + half * 8;
                        int gcol = n0 + wn + j * 8 + 2 * (lane & 3);
                        float v0 = acc[i][j][half * 2] + bvec[gcol];
                        float v1 = acc[i][j][half * 2 + 1] + bvec[gcol + 1];
                        size_t o = (size_t)grow * DD + gcol;
                        if (bz == 0) {
                            uint32_t hp, lp;
                            split_pack(v0, v1, hp, lp);
                            *reinterpret_cast<uint32_t*>(&g_Qh[o]) = hp;
                            *reinterpret_cast<uint32_t*>(&g_Ql[o]) = lp;
                        } else {
                            __half2 hv = {__float2half(v0), __float2half(v1)};
                            *reinterpret_cast<__half2*>(&g_Kh[o]) = hv;
                        }
                    }
        }
    } else {
#pragma unroll
        for (int i = 0; i < 2; i++)
#pragma unroll
            for (int j = 0; j < 8; j++)
#pragma unroll
                for (int half = 0; half < 2; half++) {
                    int grow = m0 + wm + i * 16 + (lane >> 2) + half * 8;
                    int gcol = n0 + wn + j * 8 + 2 * (lane & 3);
                    float v0 = acc[i][j][half * 2];
                    float v1 = acc[i][j][half * 2 + 1];
                    if constexpr (MODE == 3) {
                        uint32_t hp, lp;
                        split_pack(v0 * SCALE, v1 * SCALE, hp, lp);
                        size_t o = ((size_t)bz * TT + grow) * TT + gcol;
                        *reinterpret_cast<uint32_t*>(&g_Sh[o]) = hp;
                        *reinterpret_cast<uint32_t*>(&g_Sl[o]) = lp;
                    } else if constexpr (MODE == 4) {
                        size_t o = ((size_t)bz * TT + grow) * DD + gcol;
                        __half2 hv = {__float2half(v0), __float2half(v1)};
                        *reinterpret_cast<__half2*>(&g_valh[o]) = hv;
                    } else if constexpr (MODE == 5) {
                        v0 = fmaxf(v0 + bias[gcol], 0.f);
                        v1 = fmaxf(v1 + bias[gcol + 1], 0.f);
                        size_t o = (size_t)grow * DD + gcol;
                        __half2 hv = {__float2half(v0), __float2half(v1)};
                        *reinterpret_cast<__half2*>(&g_hh[o]) = hv;
                    } else if constexpr (MODE == 6) {
                        int b = grow >> 10, t = grow & 1023;
                        int L = vlen_of(vlen, b);
                        float valid = (t < L) ? 1.f : 0.f;
                        size_t o = (size_t)grow * DD + gcol;
                        float2 a2 = *reinterpret_cast<const float2*>(&xin[o]);
                        float g0 = valid / (1.f + expf(-(v0 + bias[gcol])));
                        float g1 = valid / (1.f + expf(-(v1 + bias[gcol + 1])));
                        __half2 hv = {__float2half(a2.x * g0 + a2.x),
                                      __float2half(a2.y * g1 + a2.y)};
                        *reinterpret_cast<__half2*>(&g_enhh[o]) = hv;
                    } else {  // MODE 7
                        size_t o = (size_t)grow * DD + gcol;
                        float2 r2 = {v0 + bias[gcol], v1 + bias[gcol + 1]};
                        *reinterpret_cast<float2*>(&fout[o]) = r2;
                    }
                }
    }
}

// =================== launch ================================================
extern "C" void kernel_launch(void* const* d_in, const int* in_sizes, int n_in,
                              void* d_out, int out_size) {
    const float* aud = (const float*)d_in[0];
    const float* vid = (const float*)d_in[1];
    const int*   vl  = (const int*)  d_in[2];
    const float* Wq  = (const float*)d_in[3];
    const float* bq  = (const float*)d_in[4];
    const float* Wk  = (const float*)d_in[5];
    const float* bk  = (const float*)d_in[6];
    const float* Wv  = (const float*)d_in[7];
    const float* bv  = (const float*)d_in[8];
    const float* Wc1 = (const float*)d_in[9];
    const float* bc1 = (const float*)d_in[10];
    const float* Wc2 = (const float*)d_in[11];
    const float* bc2 = (const float*)d_in[12];
    const float* Wf  = (const float*)d_in[13];
    const float* bf  = (const float*)d_in[14];
    float* out = (float*)d_out;

    const int SM = 196608;   // 3 stages x 64 KB
    cudaFuncSetAttribute(gemm_kernel<0>, cudaFuncAttributeMaxDynamicSharedMemorySize, SM);
    cudaFuncSetAttribute(gemm_kernel<3>, cudaFuncAttributeMaxDynamicSharedMemorySize, SM);
    cudaFuncSetAttribute(gemm_kernel<4>, cudaFuncAttributeMaxDynamicSharedMemorySize, SM);
    cudaFuncSetAttribute(gemm_kernel<5>, cudaFuncAttributeMaxDynamicSharedMemorySize, SM);
    cudaFuncSetAttribute(gemm_kernel<6>, cudaFuncAttributeMaxDynamicSharedMemorySize, SM);
    cudaFuncSetAttribute(gemm_kernel<7>, cudaFuncAttributeMaxDynamicSharedMemorySize, SM);

    __half *wq, *wk, *wv, *w1, *w2, *wf, *ah, *vh;
    cudaGetSymbolAddress((void**)&wq, g_Wqt);
    cudaGetSymbolAddress((void**)&wk, g_Wkt);
    cudaGetSymbolAddress((void**)&wv, g_Wvt);
    cudaGetSymbolAddress((void**)&w1, g_Wc1t);
    cudaGetSymbolAddress((void**)&w2, g_Wc2t);
    cudaGetSymbolAddress((void**)&wf, g_Wft);
    cudaGetSymbolAddress((void**)&ah, g_audh);
    cudaGetSymbolAddress((void**)&vh, g_vidh);

    cvt_kernel<<<MTOT * DD / 2048, 256>>>(aud, ah);
    cvt_kernel<<<MTOT * DD / 2048, 256>>>(vid, vh);
    wtrans6_kernel<<<dim3(16, 48, 6), 256>>>(Wq, Wk, Wv, Wc1, Wc2, Wf,
                                             wq, wk, wv, w1, w2, wf);

    gemm_kernel<0><<<dim3(2, 128, 3), NTHREADS, SM>>>(bq, nullptr, vl, nullptr, bk, bv);
    gemm_kernel<3><<<dim3(4, 8, 16), NTHREADS, SM>>>(nullptr, nullptr, vl, nullptr, nullptr, nullptr);
    softmax_kernel<<<MTOT, 256>>>(vl);
    gemm_kernel<4><<<dim3(2, 8, 16), NTHREADS, SM>>>(nullptr, nullptr, vl, nullptr, nullptr, nullptr);
    gemm_kernel<5><<<dim3(2, 128), NTHREADS, SM>>>(bc1, nullptr, vl, nullptr, nullptr, nullptr);
    gemm_kernel<6><<<dim3(2, 128), NTHREADS, SM>>>(bc2, aud, vl, nullptr, nullptr, nullptr);
    gemm_kernel<7><<<dim3(2, 128), NTHREADS, SM>>>(bf, nullptr, vl, out, nullptr, nullptr);
}

// round 16
// speedup vs baseline: 1.5717x; 1.0688x over previous
#include <cuda_runtime.h>
#include <cuda_fp16.h>
#include <math.h>
#include <stdint.h>

// Problem constants
#define BB 16
#define TT 1024
#define DD 512
#define MTOT (BB * TT)                  // 16384
#define SCALE 0.04419417382415922f      // 1/sqrt(512)

// =================== helpers (plain sm_80+ features only) ==================
__device__ __forceinline__ uint32_t smem_u32_of(const void* p) {
    uint32_t a;
    asm("{ .reg .u64 t; cvta.to.shared.u64 t, %1; cvt.u32.u64 %0, t; }"
        : "=r"(a) : "l"(p));
    return a;
}
__device__ __forceinline__ void cpa16(uint32_t dst, const void* src) {
    asm volatile("cp.async.cg.shared.global [%0], [%1], 16;"
                 :: "r"(dst), "l"(src));
}
__device__ __forceinline__ void cpa16z(uint32_t dst, const void* src, int sz) {
    asm volatile("cp.async.cg.shared.global [%0], [%1], 16, %2;"
                 :: "r"(dst), "l"(src), "r"(sz));
}
#define CP_COMMIT() asm volatile("cp.async.commit_group;" ::: "memory")
#define CP_WAIT0()  asm volatile("cp.async.wait_group 0;" ::: "memory")
#define CP_WAIT1()  asm volatile("cp.async.wait_group 1;" ::: "memory")

__device__ __forceinline__ void ldm4(uint32_t r[4], uint32_t addr) {
    asm volatile("ldmatrix.sync.aligned.m8n8.x4.shared.b16 {%0,%1,%2,%3}, [%4];"
                 : "=r"(r[0]), "=r"(r[1]), "=r"(r[2]), "=r"(r[3]) : "r"(addr));
}
#define MMA_F16(c, a, b0, b1)                                                  \
    asm volatile("mma.sync.aligned.m16n8k16.row.col.f32.f16.f16.f32 "          \
        "{%0,%1,%2,%3},{%4,%5,%6,%7},{%8,%9},{%0,%1,%2,%3};"                   \
        : "+f"((c)[0]), "+f"((c)[1]), "+f"((c)[2]), "+f"((c)[3])               \
        : "r"((a)[0]), "r"((a)[1]), "r"((a)[2]), "r"((a)[3]),                  \
          "r"(b0), "r"(b1))

__device__ __forceinline__ uint32_t sw128(uint32_t off) {
    return off ^ ((off >> 3) & 0x70);
}

// =================== scratch (fp16; ~167 MB) ===============================
__device__ __half g_audh[MTOT * DD];                      // aud fp16 hi
__device__ __half g_vidh[MTOT * DD];                      // vid fp16 hi
__device__ __half g_Qh[MTOT * DD];                        // Q hi (scores A)
__device__ __half g_Kh[MTOT * DD];                        // K hi (scores B)
__device__ __half g_Vth[MTOT * DD];                       // V^T hi [b][d][t]
__device__ __half g_Sh[BB * TT * TT], g_Sl[BB * TT * TT]; // logits pair -> probs hi
// dead-buffer aliases (lifetimes verified disjoint)
#define g_valh g_Qh
#define g_hh   g_Kh
#define g_enhh g_Vth
// transposed weights [N, K], hi plane only
__device__ __half g_Wqt[DD * DD];
__device__ __half g_Wkt[DD * DD];
__device__ __half g_Wvt[DD * DD];
__device__ __half g_Wc1t[DD * 1536];
__device__ __half g_Wc2t[DD * DD];
__device__ __half g_Wft[DD * 1024];

__device__ __forceinline__ void split2(float v, __half& h, __half& l) {
    h = __float2half(v);
    l = __float2half(v - __half2float(h));
}
__device__ __forceinline__ void split_pack(float v0, float v1,
                                           uint32_t& hp, uint32_t& lp) {
    __half h0, l0, h1, l1;
    split2(v0, h0, l0);
    split2(v1, h1, l1);
    hp = (uint32_t)__half_as_ushort(h0) | ((uint32_t)__half_as_ushort(h1) << 16);
    lp = (uint32_t)__half_as_ushort(l0) | ((uint32_t)__half_as_ushort(l1) << 16);
}
__device__ __forceinline__ int vlen_of(const int* __restrict__ vl, int b) {
    int stride = (vl[1] == 0) ? 2 : 1;   // int64 vs int32 (values in [1,1024])
    return vl[b * stride];
}

// =================== prep: fp32 -> fp16 hi conversion ======================
__global__ __launch_bounds__(256)
void cvt_kernel(const float* __restrict__ X, __half* __restrict__ Y) {
    int i = (blockIdx.x * 256 + threadIdx.x) * 8;
    float4 v0 = *reinterpret_cast<const float4*>(X + i);
    float4 v1 = *reinterpret_cast<const float4*>(X + i + 4);
    float xs[8] = {v0.x, v0.y, v0.z, v0.w, v1.x, v1.y, v1.z, v1.w};
    __half h[8];
#pragma unroll
    for (int c = 0; c < 8; c++) h[c] = __float2half(xs[c]);
    *reinterpret_cast<uint4*>(Y + i) = *reinterpret_cast<uint4*>(h);
}

// =================== prep: all 6 weight transposes in one launch ===========
__global__ __launch_bounds__(256)
void wtrans6_kernel(const float* __restrict__ W0, const float* __restrict__ W1,
                    const float* __restrict__ W2, const float* __restrict__ W3,
                    const float* __restrict__ W4, const float* __restrict__ W5,
                    __half* __restrict__ T0, __half* __restrict__ T1,
                    __half* __restrict__ T2, __half* __restrict__ T3,
                    __half* __restrict__ T4, __half* __restrict__ T5) {
    int z = blockIdx.z;
    const float* W = (z == 0) ? W0 : (z == 1) ? W1 : (z == 2) ? W2
                   : (z == 3) ? W3 : (z == 4) ? W4 : W5;
    __half* T = (z == 0) ? T0 : (z == 1) ? T1 : (z == 2) ? T2
              : (z == 3) ? T3 : (z == 4) ? T4 : T5;
    int K = (z == 3) ? 1536 : (z == 5) ? 1024 : 512;
    int k0 = blockIdx.y * 32;
    if (k0 >= K) return;
    __shared__ float t[32][33];
    int n0 = blockIdx.x * 32;
    int tx = threadIdx.x & 31, ty = threadIdx.x >> 5;
    for (int i = ty; i < 32; i += 8)
        t[i][tx] = W[(size_t)(k0 + i) * 512 + n0 + tx];
    __syncthreads();
    for (int i = ty; i < 32; i += 8)
        T[(size_t)(n0 + i) * K + k0 + tx] = __float2half(t[tx][i]);
}

// =================== masked softmax: logits pair -> probs hi ===============
__global__ __launch_bounds__(256)
void softmax_kernel(const int* __restrict__ vl) {
    __shared__ float red[8];
    int row = blockIdx.x;
    int b = row >> 10;
    int L = vlen_of(vl, b);
    int Lc = (L + 63) & ~63;            // PV reads cols < ceil64(L) only
    size_t rbase = (size_t)row * TT;
    int tid = threadIdx.x, lane = tid & 31, wid = tid >> 5;
    int k0 = tid * 4;
    float xs[4];
    if (k0 < L) {
#pragma unroll
        for (int c = 0; c < 4; c++)
            xs[c] = __half2float(g_Sh[rbase + k0 + c]) +
                    __half2float(g_Sl[rbase + k0 + c]);
    } else {
#pragma unroll
        for (int c = 0; c < 4; c++) xs[c] = -3.4e38f;
    }
    float m = -3.4e38f;
#pragma unroll
    for (int c = 0; c < 4; c++)
        if (k0 + c < L) m = fmaxf(m, xs[c]);
#pragma unroll
    for (int s = 16; s > 0; s >>= 1)
        m = fmaxf(m, __shfl_xor_sync(0xffffffffu, m, s));
    if (lane == 0) red[wid] = m;
    __syncthreads();
    if (wid == 0) {
        float t = red[lane & 7];
#pragma unroll
        for (int s = 4; s > 0; s >>= 1)
            t = fmaxf(t, __shfl_xor_sync(0xffffffffu, t, s));
        if (lane == 0) red[0] = t;
    }
    __syncthreads();
    float rm = red[0];
    float e[4], sum = 0.f;
#pragma unroll
    for (int c = 0; c < 4; c++) {
        e[c] = (k0 + c < L) ? expf(xs[c] - rm) : 0.f;
        sum += e[c];
    }
#pragma unroll
    for (int s = 16; s > 0; s >>= 1)
        sum += __shfl_xor_sync(0xffffffffu, sum, s);
    __syncthreads();
    if (lane == 0) red[wid] = sum;
    __syncthreads();
    if (wid == 0) {
        float t = red[lane & 7];
#pragma unroll
        for (int s = 4; s > 0; s >>= 1)
            t += __shfl_xor_sync(0xffffffffu, t, s);
        if (lane == 0) red[0] = t;
    }
    __syncthreads();
    if (k0 < Lc) {
        float inv = 1.f / red[0];
        __half hb[4];
#pragma unroll
        for (int c = 0; c < 4; c++)
            hb[c] = __float2half(e[c] * inv);
        *reinterpret_cast<uint2*>(&g_Sh[rbase + k0]) =
            *reinterpret_cast<uint2*>(hb);
    }
}

// ============ mma.sync GEMM, 128x256 tiles, 512 threads, 3-stage ===========
// MODE: 0=QKVproj(bz sel) 3=scores 4=PV 5=conv1 6=gate 7=final
// SMEM stage: [Ah 16K][pad 16K][Bh 32K] = 64 KB x3 = 192 KB
#define SA_H 0
#define SB_H 32768
#define STAGE_BYTES 65536
#define NTHREADS 512

__device__ __forceinline__ void load_tileB(uint32_t sbase, int stage,
        const __half* __restrict__ Bh, int n0, int ldb, int kc, int tid) {
    uint32_t dh = sbase + stage * STAGE_BYTES + SB_H;
#pragma unroll
    for (int it = 0; it < 4; it++) {               // 256 rows x 8 cols / 512 thr
        int idx = it * NTHREADS + tid;
        int r = idx >> 3, c8 = idx & 7;
        size_t off = (size_t)(n0 + r) * ldb + kc * 64 + c8 * 8;
        uint32_t so = sw128((uint32_t)(r * 128 + c8 * 16));
        cpa16(dh + so, Bh + off);
    }
}

template <int MODE>
__device__ __forceinline__ void load_tileA(uint32_t sbase, int stage,
        const __half* __restrict__ Ah, int m0, int lda, int kc, int tid) {
    uint32_t dhu = sbase + stage * STAGE_BYTES + SA_H;
#pragma unroll
    for (int it = 0; it < 2; it++) {               // 128 rows x 8 cols / 512 thr
        int idx = it * NTHREADS + tid;
        int r = idx >> 3, c8 = idx & 7;
        uint32_t so = sw128((uint32_t)(r * 128 + c8 * 16));
        if constexpr (MODE == 5) {
            int gr = m0 + r, b = gr >> 10, t = gr & 1023;
            int ts = t + (kc >> 3) - 1;
            int ok = ((unsigned)ts < (unsigned)TT) ? 16 : 0;
            int tsc = min(max(ts, 0), TT - 1);
            size_t off = (size_t)((b << 10) + tsc) * DD + (kc & 7) * 64 + c8 * 8;
            cpa16z(dhu + so, g_valh + off, ok);
        } else if constexpr (MODE == 7) {
            int gr = m0 + r;
            const __half* src = (kc < 8) ? g_enhh : g_vidh;
            int kk = (kc < 8) ? kc : (kc - 8);
            size_t off = (size_t)gr * DD + kk * 64 + c8 * 8;
            cpa16(dhu + so, src + off);
        } else {
            // MODE 0 (audh/vidh), MODE 3 (Q hi), MODE 4 (P hi), MODE 6 (h hi)
            size_t off = (size_t)(m0 + r) * lda + kc * 64 + c8 * 8;
            cpa16(dhu + so, Ah + off);
        }
    }
}

template <int MODE>
__global__ __launch_bounds__(NTHREADS)
void gemm_kernel(const float* __restrict__ bias, const float* __restrict__ xin,
                 const int* __restrict__ vlen, float* __restrict__ fout,
                 const float* __restrict__ bias1, const float* __restrict__ bias2) {
    constexpr int KTOT = (MODE == 5) ? 1536 : ((MODE == 4 || MODE == 7) ? 1024 : 512);
    constexpr int KT = KTOT / 64;

    extern __shared__ char smem[];
    int tid = threadIdx.x, wid = tid >> 5, lane = tid & 31;
    int bx = blockIdx.x, by = blockIdx.y, bz = blockIdx.z;
    uint32_t sbase = smem_u32_of(smem);
    int m0 = by * 128, n0 = bx * 256;

    // ---- mask-based CTA skips (bit-exact) ----
    int ktEnd = KT;
    if constexpr (MODE == 3) {
        int L = vlen_of(vlen, bz);
        if (n0 >= L) return;             // keys all masked by softmax
    }
    if constexpr (MODE == 4) {
        int L = vlen_of(vlen, bz);
        if (m0 > L) return;              // value[t] unused for t > L
        ktEnd = min(KT, (L + 63) >> 6);  // P cols >= L are exact zeros
    }
    if constexpr (MODE == 5) {
        int L = vlen_of(vlen, m0 >> 10);
        if ((m0 & 1023) >= L) return;    // h[t] gated to zero for t >= L
    }

    const __half *Ah = nullptr, *Bh = nullptr;
    const float* bvec = bias;
    int lda = 512, ldb = 512;
    if constexpr (MODE == 0) {
        // bz: 0=Q(aud,Wq) 1=K(vid,Wk) 2=V(vid,Wv)
        Ah = (bz == 0) ? g_audh : g_vidh;
        Bh = (bz == 0) ? g_Wqt : (bz == 1) ? g_Wkt : g_Wvt;
        bvec = (bz == 0) ? bias : (bz == 1) ? bias1 : bias2;
    }
    if constexpr (MODE == 3) {
        size_t bo = (size_t)bz * TT * DD;
        Ah = g_Qh + bo; Bh = g_Kh + bo;
    }
    if constexpr (MODE == 4) {
        Ah = g_Sh + (size_t)bz * TT * TT; lda = 1024;
        Bh = g_Vth + (size_t)bz * DD * TT; ldb = 1024;
    }
    if constexpr (MODE == 5) { Bh = g_Wc1t; ldb = 1536; }
    if constexpr (MODE == 6) { Ah = g_hh; Bh = g_Wc2t; }
    if constexpr (MODE == 7) { Bh = g_Wft; ldb = 1024; }

    // 16 warps: 4 (M) x 4 (N); warp tile 32x64
    int wm = (wid & 3) * 32, wn = (wid >> 2) * 64;
    float acc[2][8][4];
#pragma unroll
    for (int i = 0; i < 2; i++)
#pragma unroll
        for (int j = 0; j < 8; j++)
#pragma unroll
            for (int c = 0; c < 4; c++) acc[i][j][c] = 0.f;

    // prologue: chunks 0,1 -> stages 0,1
    load_tileA<MODE>(sbase, 0, Ah, m0, lda, 0, tid);
    load_tileB(sbase, 0, Bh, n0, ldb, 0, tid);
    CP_COMMIT();
    load_tileA<MODE>(sbase, 1, Ah, m0, lda, 1, tid);
    load_tileB(sbase, 1, Bh, n0, ldb, 1, tid);
    CP_COMMIT();

    int a_r = (lane & 7) + ((lane >> 3) & 1) * 8;
    int a_c = ((lane >> 4) & 1) * 16;
    int b_r = (lane & 7) + ((lane >> 4) & 1) * 8;
    int b_c = ((lane >> 3) & 1) * 16;

    int cur = 0;
    for (int kt = 0; kt < ktEnd; kt++) {
        if (kt + 1 < ktEnd) CP_WAIT1(); else CP_WAIT0();
        __syncthreads();
        if (kt + 2 < ktEnd) {
            int nxt2 = cur + 2;
            if (nxt2 >= 3) nxt2 -= 3;
            load_tileA<MODE>(sbase, nxt2, Ah, m0, lda, kt + 2, tid);
            load_tileB(sbase, nxt2, Bh, n0, ldb, kt + 2, tid);
            CP_COMMIT();
        }
        uint32_t bufb = sbase + cur * STAGE_BYTES;
#pragma unroll
        for (int ks = 0; ks < 4; ks++) {
            int kb = ks * 32;
            uint32_t ahf[2][4];
#pragma unroll
            for (int i = 0; i < 2; i++) {
                uint32_t so = sw128((uint32_t)((wm + i * 16 + a_r) * 128 + kb + a_c));
                ldm4(ahf[i], bufb + SA_H + so);
            }
#pragma unroll
            for (int j2 = 0; j2 < 4; j2++) {
                uint32_t so = sw128((uint32_t)((wn + j2 * 16 + b_r) * 128 + kb + b_c));
                uint32_t tb[4];
                ldm4(tb, bufb + SB_H + so);
#pragma unroll
                for (int i = 0; i < 2; i++) {
                    MMA_F16(acc[i][2 * j2],     ahf[i], tb[0], tb[1]);
                    MMA_F16(acc[i][2 * j2 + 1], ahf[i], tb[2], tb[3]);
                }
            }
        }
        cur++;
        if (cur == 3) cur = 0;
    }

    // ---------------- epilogue ----------------
    if constexpr (MODE == 0) {
        if (bz == 2) {
            // V: stage fp32 in smem, then write V^T (hi plane only)
            __syncthreads();
            float* s = reinterpret_cast<float*>(smem);   // 128 x 264 fp32
#pragma unroll
            for (int i = 0; i < 2; i++)
#pragma unroll
                for (int j = 0; j < 8; j++) {
                    int r0 = wm + i * 16 + (lane >> 2);
                    int c = wn + j * 8 + 2 * (lane & 3);
                    s[r0 * 264 + c]           = acc[i][j][0] + bvec[n0 + c];
                    s[r0 * 264 + c + 1]       = acc[i][j][1] + bvec[n0 + c + 1];
                    s[(r0 + 8) * 264 + c]     = acc[i][j][2] + bvec[n0 + c];
                    s[(r0 + 8) * 264 + c + 1] = acc[i][j][3] + bvec[n0 + c + 1];
                }
            __syncthreads();
            int d = tid & 255;
            int mh = (tid >> 8) * 64;
            int b = m0 >> 10, t0 = m0 & 1023;
            size_t obase = ((size_t)b * DD + n0 + d) * TT + t0 + mh;
            for (int m = 0; m < 64; m += 8) {
                __half hb[8];
#pragma unroll
                for (int q = 0; q < 8; q++)
                    hb[q] = __float2half(s[(mh + m + q) * 264 + d]);
                *reinterpret_cast<uint4*>(&g_Vth[obase + m]) =
                    *reinterpret_cast<uint4*>(hb);
            }
        } else {
#pragma unroll
            for (int i = 0; i < 2; i++)
#pragma unroll
                for (int j = 0; j < 8; j++)
#pragma unroll
                    for (int half = 0; half < 2; half++) {
                        int grow = m0 + wm + i * 16 + (lane >> 2) + half * 8;
                        int gcol = n0 + wn + j * 8 + 2 * (lane & 3);
                        float v0 = acc[i][j][half * 2] + bvec[gcol];
                        float v1 = acc[i][j][half * 2 + 1] + bvec[gcol + 1];
                        size_t o = (size_t)grow * DD + gcol;
                        __half2 hv = {__float2half(v0), __float2half(v1)};
                        if (bz == 0)
                            *reinterpret_cast<__half2*>(&g_Qh[o]) = hv;
                        else
                            *reinterpret_cast<__half2*>(&g_Kh[o]) = hv;
                    }
        }
    } else {
#pragma unroll
        for (int i = 0; i < 2; i++)
#pragma unroll
            for (int j = 0; j < 8; j++)
#pragma unroll
                for (int half = 0; half < 2; half++) {
                    int grow = m0 + wm + i * 16 + (lane >> 2) + half * 8;
                    int gcol = n0 + wn + j * 8 + 2 * (lane & 3);
                    float v0 = acc[i][j][half * 2];
                    float v1 = acc[i][j][half * 2 + 1];
                    if constexpr (MODE == 3) {
                        uint32_t hp, lp;
                        split_pack(v0 * SCALE, v1 * SCALE, hp, lp);
                        size_t o = ((size_t)bz * TT + grow) * TT + gcol;
                        *reinterpret_cast<uint32_t*>(&g_Sh[o]) = hp;
                        *reinterpret_cast<uint32_t*>(&g_Sl[o]) = lp;
                    } else if constexpr (MODE == 4) {
                        size_t o = ((size_t)bz * TT + grow) * DD + gcol;
                        __half2 hv = {__float2half(v0), __float2half(v1)};
                        *reinterpret_cast<__half2*>(&g_valh[o]) = hv;
                    } else if constexpr (MODE == 5) {
                        v0 = fmaxf(v0 + bias[gcol], 0.f);
                        v1 = fmaxf(v1 + bias[gcol + 1], 0.f);
                        size_t o = (size_t)grow * DD + gcol;
                        __half2 hv = {__float2half(v0), __float2half(v1)};
                        *reinterpret_cast<__half2*>(&g_hh[o]) = hv;
                    } else if constexpr (MODE == 6) {
                        int b = grow >> 10, t = grow & 1023;
                        int L = vlen_of(vlen, b);
                        float valid = (t < L) ? 1.f : 0.f;
                        size_t o = (size_t)grow * DD + gcol;
                        float2 a2 = *reinterpret_cast<const float2*>(&xin[o]);
                        float g0 = valid / (1.f + expf(-(v0 + bias[gcol])));
                        float g1 = valid / (1.f + expf(-(v1 + bias[gcol + 1])));
                        __half2 hv = {__float2half(a2.x * g0 + a2.x),
                                      __float2half(a2.y * g1 + a2.y)};
                        *reinterpret_cast<__half2*>(&g_enhh[o]) = hv;
                    } else {  // MODE 7
                        size_t o = (size_t)grow * DD + gcol;
                        float2 r2 = {v0 + bias[gcol], v1 + bias[gcol + 1]};
                        *reinterpret_cast<float2*>(&fout[o]) = r2;
                    }
                }
    }
}

// =================== launch ================================================
extern "C" void kernel_launch(void* const* d_in, const int* in_sizes, int n_in,
                              void* d_out, int out_size) {
    const float* aud = (const float*)d_in[0];
    const float* vid = (const float*)d_in[1];
    const int*   vl  = (const int*)  d_in[2];
    const float* Wq  = (const float*)d_in[3];
    const float* bq  = (const float*)d_in[4];
    const float* Wk  = (const float*)d_in[5];
    const float* bk  = (const float*)d_in[6];
    const float* Wv  = (const float*)d_in[7];
    const float* bv  = (const float*)d_in[8];
    const float* Wc1 = (const float*)d_in[9];
    const float* bc1 = (const float*)d_in[10];
    const float* Wc2 = (const float*)d_in[11];
    const float* bc2 = (const float*)d_in[12];
    const float* Wf  = (const float*)d_in[13];
    const float* bf  = (const float*)d_in[14];
    float* out = (float*)d_out;

    const int SM = 196608;   // 3 stages x 64 KB
    cudaFuncSetAttribute(gemm_kernel<0>, cudaFuncAttributeMaxDynamicSharedMemorySize, SM);
    cudaFuncSetAttribute(gemm_kernel<3>, cudaFuncAttributeMaxDynamicSharedMemorySize, SM);
    cudaFuncSetAttribute(gemm_kernel<4>, cudaFuncAttributeMaxDynamicSharedMemorySize, SM);
    cudaFuncSetAttribute(gemm_kernel<5>, cudaFuncAttributeMaxDynamicSharedMemorySize, SM);
    cudaFuncSetAttribute(gemm_kernel<6>, cudaFuncAttributeMaxDynamicSharedMemorySize, SM);
    cudaFuncSetAttribute(gemm_kernel<7>, cudaFuncAttributeMaxDynamicSharedMemorySize, SM);

    __half *wq, *wk, *wv, *w1, *w2, *wf, *ah, *vh;
    cudaGetSymbolAddress((void**)&wq, g_Wqt);
    cudaGetSymbolAddress((void**)&wk, g_Wkt);
    cudaGetSymbolAddress((void**)&wv, g_Wvt);
    cudaGetSymbolAddress((void**)&w1, g_Wc1t);
    cudaGetSymbolAddress((void**)&w2, g_Wc2t);
    cudaGetSymbolAddress((void**)&wf, g_Wft);
    cudaGetSymbolAddress((void**)&ah, g_audh);
    cudaGetSymbolAddress((void**)&vh, g_vidh);

    cvt_kernel<<<MTOT * DD / 2048, 256>>>(aud, ah);
    cvt_kernel<<<MTOT * DD / 2048, 256>>>(vid, vh);
    wtrans6_kernel<<<dim3(16, 48, 6), 256>>>(Wq, Wk, Wv, Wc1, Wc2, Wf,
                                             wq, wk, wv, w1, w2, wf);

    gemm_kernel<0><<<dim3(2, 128, 3), NTHREADS, SM>>>(bq, nullptr, vl, nullptr, bk, bv);
    gemm_kernel<3><<<dim3(4, 8, 16), NTHREADS, SM>>>(nullptr, nullptr, vl, nullptr, nullptr, nullptr);
    softmax_kernel<<<MTOT, 256>>>(vl);
    gemm_kernel<4><<<dim3(2, 8, 16), NTHREADS, SM>>>(nullptr, nullptr, vl, nullptr, nullptr, nullptr);
    gemm_kernel<5><<<dim3(2, 128), NTHREADS, SM>>>(bc1, nullptr, vl, nullptr, nullptr, nullptr);
    gemm_kernel<6><<<dim3(2, 128), NTHREADS, SM>>>(bc2, aud, vl, nullptr, nullptr, nullptr);
    gemm_kernel<7><<<dim3(2, 128), NTHREADS, SM>>>(bf, nullptr, vl, out, nullptr, nullptr);
}